// round 5
// baseline (speedup 1.0000x reference)
#include <cuda_runtime.h>
#include <stdint.h>

#define NBAT 16
#define NT 2048
#define NF 128
#define NU 256
#define NBT (NBAT*NT)

__device__ float g_q[NBT*NU];
__device__ float g_v[NBT*NU];
__device__ float g_k[NBT*NU];

#define XSTR 132   // proj X tile stride  (mod-32-words = 4: conflict-free)
#define WSTR 260   // proj W tile stride  (=4)
#define QSTR 260   // attn Q tile stride  (=4)
#define VSTR 260   // attn V/K tile stride(=4)

__device__ __forceinline__ uint32_t f2tf(float f){
    uint32_t r; asm("cvt.rna.tf32.f32 %0, %1;" : "=r"(r) : "f"(f)); return r;
}
__device__ __forceinline__ float ex2(float x){
    float r; asm("ex2.approx.f32 %0, %1;" : "=f"(r) : "f"(x)); return r;
}
__device__ __forceinline__ void mma8(float* d, uint32_t a0, uint32_t a1,
                                     uint32_t a2, uint32_t a3,
                                     uint32_t b0, uint32_t b1){
    asm volatile(
        "mma.sync.aligned.m16n8k8.row.col.f32.tf32.tf32.f32 "
        "{%0,%1,%2,%3}, {%4,%5,%6,%7}, {%8,%9}, {%0,%1,%2,%3};"
        : "+f"(d[0]), "+f"(d[1]), "+f"(d[2]), "+f"(d[3])
        : "r"(a0), "r"(a1), "r"(a2), "r"(a3), "r"(b0), "r"(b1));
}
__device__ __forceinline__ float sigmoidf(float x){
    return 1.f / (1.f + __expf(-x));
}

// ---------------------------------------------------------------------------
// Kernel 1: q/v/k = round_tf32(sigmoid(x @ W)). 128x256 tile per CTA.
// block 512 = 16 warps = 8 rowgroups x 2 N-halves; warp does 16x128 (acc 64).
// ---------------------------------------------------------------------------
__global__ __launch_bounds__(512, 1) void proj_kernel(
    const float* __restrict__ x,  const float* __restrict__ Wq,
    const float* __restrict__ Wv, const float* __restrict__ Wk)
{
    extern __shared__ float sm[];
    float* Xs = sm;                 // 128 x XSTR
    float* Ws = sm + 128 * XSTR;    // 128 x WSTR (rows = f, cols = u)

    const int tid = threadIdx.x, w = tid >> 5, lane = tid & 31;
    const int g = lane >> 2, q = lane & 3;
    const int grp = w >> 1, h = w & 1;
    const int rb = blockIdx.x * 128, z = blockIdx.y;
    const float* W  = (z == 0) ? Wq : (z == 1) ? Wv : Wk;
    float*      Out = (z == 0) ? g_q : (z == 1) ? g_v : g_k;

    #pragma unroll
    for (int i = 0; i < 8; i++){
        int idx = tid + i * 512; int r = idx >> 5, c4 = idx & 31;
        float4 v = *(const float4*)&x[(size_t)(rb + r) * NF + c4 * 4];
        float* d = &Xs[r * XSTR + c4 * 4];
        d[0] = __uint_as_float(f2tf(v.x)); d[1] = __uint_as_float(f2tf(v.y));
        d[2] = __uint_as_float(f2tf(v.z)); d[3] = __uint_as_float(f2tf(v.w));
    }
    #pragma unroll
    for (int i = 0; i < 16; i++){
        int idx = tid + i * 512; int r = idx >> 6, c4 = idx & 63;
        float4 v = *(const float4*)&W[(size_t)r * NU + c4 * 4];
        float* d = &Ws[r * WSTR + c4 * 4];
        d[0] = __uint_as_float(f2tf(v.x)); d[1] = __uint_as_float(f2tf(v.y));
        d[2] = __uint_as_float(f2tf(v.z)); d[3] = __uint_as_float(f2tf(v.w));
    }
    __syncthreads();

    float acc[16][4];
    #pragma unroll
    for (int nb = 0; nb < 16; nb++)
        #pragma unroll
        for (int e = 0; e < 4; e++) acc[nb][e] = 0.f;

    const float* Qw = Xs + (grp * 16) * XSTR;
    const int nb0 = h * 128;                 // column offset of this warp's half
    #pragma unroll 4
    for (int kb = 0; kb < 16; kb++){
        const int k0 = kb * 8;
        uint32_t a0 = __float_as_uint(Qw[g * XSTR + k0 + q]);
        uint32_t a1 = __float_as_uint(Qw[(g + 8) * XSTR + k0 + q]);
        uint32_t a2 = __float_as_uint(Qw[g * XSTR + k0 + q + 4]);
        uint32_t a3 = __float_as_uint(Qw[(g + 8) * XSTR + k0 + q + 4]);
        const float* B0 = &Ws[(k0 + q) * WSTR + nb0 + g];
        const float* B1 = &Ws[(k0 + q + 4) * WSTR + nb0 + g];
        #pragma unroll
        for (int nb = 0; nb < 16; nb++){
            uint32_t b0 = __float_as_uint(B0[nb * 8]);
            uint32_t b1 = __float_as_uint(B1[nb * 8]);
            mma8(acc[nb], a0, a1, a2, a3, b0, b1);
        }
    }

    const int r0 = rb + grp * 16 + g, r1 = r0 + 8;
    #pragma unroll
    for (int nb = 0; nb < 16; nb++){
        int c = nb0 + nb * 8 + 2 * q;
        float2 v0, v1;
        v0.x = __uint_as_float(f2tf(sigmoidf(acc[nb][0])));
        v0.y = __uint_as_float(f2tf(sigmoidf(acc[nb][1])));
        v1.x = __uint_as_float(f2tf(sigmoidf(acc[nb][2])));
        v1.y = __uint_as_float(f2tf(sigmoidf(acc[nb][3])));
        *(float2*)&Out[(size_t)r0 * NU + c] = v0;
        *(float2*)&Out[(size_t)r1 * NU + c] = v1;
    }
}

// ---------------------------------------------------------------------------
// Kernel 2: flash attention, static softmax max (q,v in (0,1)).
// block 512 = 16 warps = 8 rowgroups x 2 halves. Each warp: full S (16x64,
// duplicated in pair -> complete row sums, no exchange), half O (16x128).
// V and K share one smem buffer. grid (16 qtiles, 16 batches).
// ---------------------------------------------------------------------------
__global__ __launch_bounds__(512, 1) void attn_kernel(float* __restrict__ out)
{
    extern __shared__ float sm[];
    float* Qs = sm;                  // 128 x QSTR
    float* VK = sm + 128 * QSTR;     // 64 x VSTR (V, then K)

    const int tid = threadIdx.x, w = tid >> 5, lane = tid & 31;
    const int g = lane >> 2, q = lane & 3;
    const int grp = w >> 1, h = w & 1;
    const int qt = 15 - (int)blockIdx.x;      // big tiles first
    const int b  = blockIdx.y;
    const int t0 = qt * 128;
    const int srow0 = t0 + grp * 16 + g, srow1 = srow0 + 8;

    const float* qb = g_q + (size_t)(b * NT) * NU;
    const float* vb = g_v + (size_t)(b * NT) * NU;
    const float* kb = g_k + (size_t)(b * NT) * NU;

    #pragma unroll
    for (int i = 0; i < 16; i++){
        int idx = tid + i * 512; int r = idx >> 6, c4 = idx & 63;
        *(float4*)&Qs[r * QSTR + c4 * 4] =
            *(const float4*)&qb[(size_t)(t0 + r) * NU + c4 * 4];
    }

    float oacc[16][4];
    #pragma unroll
    for (int nb = 0; nb < 16; nb++)
        #pragma unroll
        for (int e = 0; e < 4; e++) oacc[nb][e] = 0.f;
    float l0 = 0.f, l1 = 0.f;

    const float C1 = 0.127517906167328651f;   // (1/sqrt(128)) * log2(e)
    const float C2 = 32.6444645f;             // 22.627417 * log2(e) static max

    const int base = lane & ~3;
    const int src0 = base + (q >> 1), src1 = src0 + 2;
    const bool odd = q & 1;
    const int nb0 = h * 128;

    const int jn = 2 * qt + 2;
    for (int j = 0; j < jn; j++){
        const int s0 = j * 64;
        __syncthreads();                       // prev O-GEMM done with VK
        #pragma unroll
        for (int i = 0; i < 8; i++){
            int idx = tid + i * 512; int r = idx >> 6, c4 = idx & 63;
            *(float4*)&VK[r * VSTR + c4 * 4] =
                *(const float4*)&vb[(size_t)(s0 + r) * NU + c4 * 4];
        }
        __syncthreads();

        // ---- S = Q . V^T (full 16x64 per warp, duplicated in pair) ----
        float sacc[8][4];
        #pragma unroll
        for (int nb = 0; nb < 8; nb++)
            #pragma unroll
            for (int e = 0; e < 4; e++) sacc[nb][e] = 0.f;

        const float* Qw = Qs + (grp * 16) * QSTR;
        #pragma unroll 4
        for (int kc = 0; kc < 32; kc++){
            const int k0 = kc * 8;
            uint32_t a0 = __float_as_uint(Qw[g * QSTR + k0 + q]);
            uint32_t a1 = __float_as_uint(Qw[(g + 8) * QSTR + k0 + q]);
            uint32_t a2 = __float_as_uint(Qw[g * QSTR + k0 + q + 4]);
            uint32_t a3 = __float_as_uint(Qw[(g + 8) * QSTR + k0 + q + 4]);
            const float* B0 = &VK[g * VSTR + k0 + q];
            #pragma unroll
            for (int nb = 0; nb < 8; nb++){
                uint32_t b0 = __float_as_uint(B0[nb * 8 * VSTR]);
                uint32_t b1 = __float_as_uint(B0[nb * 8 * VSTR + 4]);
                mma8(sacc[nb], a0, a1, a2, a3, b0, b1);
            }
        }

        // ---- softmax with static max; complete row sums ----
        float pl0 = 0.f, pl1 = 0.f;
        #pragma unroll
        for (int nb = 0; nb < 8; nb++){
            int c0 = s0 + nb * 8 + 2 * q;
            float p0 = (c0     < srow0) ? ex2(fmaf(sacc[nb][0], C1, -C2)) : 0.f;
            float p1 = (c0 + 1 < srow0) ? ex2(fmaf(sacc[nb][1], C1, -C2)) : 0.f;
            float p2 = (c0     < srow1) ? ex2(fmaf(sacc[nb][2], C1, -C2)) : 0.f;
            float p3 = (c0 + 1 < srow1) ? ex2(fmaf(sacc[nb][3], C1, -C2)) : 0.f;
            pl0 += p0 + p1; pl1 += p2 + p3;
            sacc[nb][0] = p0; sacc[nb][1] = p1;
            sacc[nb][2] = p2; sacc[nb][3] = p3;
        }
        pl0 += __shfl_xor_sync(~0u, pl0, 1); pl0 += __shfl_xor_sync(~0u, pl0, 2);
        pl1 += __shfl_xor_sync(~0u, pl1, 1); pl1 += __shfl_xor_sync(~0u, pl1, 2);
        l0 += pl0; l1 += pl1;

        __syncthreads();                       // all warps done reading V
        #pragma unroll
        for (int i = 0; i < 8; i++){
            int idx = tid + i * 512; int r = idx >> 6, c4 = idx & 63;
            *(float4*)&VK[r * VSTR + c4 * 4] =
                *(const float4*)&kb[(size_t)(s0 + r) * NU + c4 * 4];
        }
        __syncthreads();

        // ---- O(16x128 half) += P . K ; C->A conversion folded per kc ----
        #pragma unroll
        for (int kc = 0; kc < 8; kc++){
            float x0 = __shfl_sync(~0u, sacc[kc][0], src0);
            float x1 = __shfl_sync(~0u, sacc[kc][1], src0);
            float x2 = __shfl_sync(~0u, sacc[kc][2], src0);
            float x3 = __shfl_sync(~0u, sacc[kc][3], src0);
            float y0 = __shfl_sync(~0u, sacc[kc][0], src1);
            float y1 = __shfl_sync(~0u, sacc[kc][1], src1);
            float y2 = __shfl_sync(~0u, sacc[kc][2], src1);
            float y3 = __shfl_sync(~0u, sacc[kc][3], src1);
            uint32_t pa0 = __float_as_uint(odd ? x1 : x0);
            uint32_t pa1 = __float_as_uint(odd ? x3 : x2);
            uint32_t pa2 = __float_as_uint(odd ? y1 : y0);
            uint32_t pa3 = __float_as_uint(odd ? y3 : y2);
            const float* B0 = &VK[(kc * 8 + q) * VSTR + nb0 + g];
            const float* B1 = &VK[(kc * 8 + q + 4) * VSTR + nb0 + g];
            #pragma unroll
            for (int nb = 0; nb < 16; nb++){
                uint32_t b0 = __float_as_uint(B0[nb * 8]);
                uint32_t b1 = __float_as_uint(B1[nb * 8]);
                mma8(oacc[nb], pa0, pa1, pa2, pa3, b0, b1);
            }
        }
    }

    // ---- epilogue: normalize; row t==0 forced to zeros ----
    const float inv0 = (srow0 == 0) ? 0.f : 1.f / l0;
    const float inv1 = 1.f / l1;
    float* o0 = out + ((size_t)b * NT + srow0) * NU + nb0;
    float* o1 = out + ((size_t)b * NT + srow1) * NU + nb0;
    #pragma unroll
    for (int nb = 0; nb < 16; nb++){
        int c = nb * 8 + 2 * q;
        float2 v0, v1;
        v0.x = oacc[nb][0] * inv0; v0.y = oacc[nb][1] * inv0;
        v1.x = oacc[nb][2] * inv1; v1.y = oacc[nb][3] * inv1;
        *(float2*)&o0[c] = v0;
        *(float2*)&o1[c] = v1;
    }
}

// ---------------------------------------------------------------------------
extern "C" void kernel_launch(void* const* d_in, const int* in_sizes, int n_in,
                              void* d_out, int out_size)
{
    const float* x  = (const float*)d_in[0];
    const float* Wq = (const float*)d_in[1];
    const float* Wv = (const float*)d_in[2];
    const float* Wk = (const float*)d_in[3];
    float* out = (float*)d_out;

    const int smem1 = (128 * XSTR + 128 * WSTR) * 4;   // 200,704 B
    const int smem2 = (128 * QSTR + 64 * VSTR) * 4;    // 199,680 B
    cudaFuncSetAttribute(proj_kernel, cudaFuncAttributeMaxDynamicSharedMemorySize, smem1);
    cudaFuncSetAttribute(attn_kernel, cudaFuncAttributeMaxDynamicSharedMemorySize, smem2);

    proj_kernel<<<dim3(NBT / 128, 3), 512, smem1>>>(x, Wq, Wv, Wk);
    attn_kernel<<<dim3(16, 16), 512, smem2>>>(out);
}

// round 7
// speedup vs baseline: 2.6722x; 2.6722x over previous
#include <cuda_runtime.h>
#include <cuda_fp16.h>
#include <stdint.h>

#define NBAT 16
#define NT 2048
#define NF 128
#define NU 256
#define NBT (NBAT*NT)

__device__ __half g_q[NBT*NU];
__device__ __half g_v[NBT*NU];
__device__ __half g_k[NBT*NU];

#define XS2 136   // proj X tile stride in halves (272B: 16B phase shift/row)
#define WS2 264   // proj W tile stride (528B)
#define QS2 264   // attn Q stride
#define VS2 264   // attn V/K stride

__device__ __forceinline__ uint32_t sptr(const void* p){
    return (uint32_t)__cvta_generic_to_shared(p);
}
__device__ __forceinline__ void ldsm4(uint32_t* d, uint32_t a){
    asm volatile("ldmatrix.sync.aligned.m8n8.x4.shared.b16 {%0,%1,%2,%3}, [%4];"
        : "=r"(d[0]),"=r"(d[1]),"=r"(d[2]),"=r"(d[3]) : "r"(a));
}
__device__ __forceinline__ void ldsm4t(uint32_t* d, uint32_t a){
    asm volatile("ldmatrix.sync.aligned.m8n8.x4.trans.shared.b16 {%0,%1,%2,%3}, [%4];"
        : "=r"(d[0]),"=r"(d[1]),"=r"(d[2]),"=r"(d[3]) : "r"(a));
}
__device__ __forceinline__ void hmma(float* d, const uint32_t* A, uint32_t b0, uint32_t b1){
    asm volatile("mma.sync.aligned.m16n8k16.row.col.f32.f16.f16.f32 "
        "{%0,%1,%2,%3}, {%4,%5,%6,%7}, {%8,%9}, {%0,%1,%2,%3};"
        : "+f"(d[0]),"+f"(d[1]),"+f"(d[2]),"+f"(d[3])
        : "r"(A[0]),"r"(A[1]),"r"(A[2]),"r"(A[3]), "r"(b0),"r"(b1));
}
__device__ __forceinline__ uint32_t packh2(float lo, float hi){
    uint32_t r; asm("cvt.rn.f16x2.f32 %0, %1, %2;" : "=r"(r) : "f"(hi), "f"(lo));
    return r;
}
__device__ __forceinline__ float ex2(float x){
    float r; asm("ex2.approx.f32 %0, %1;" : "=f"(r) : "f"(x)); return r;
}
__device__ __forceinline__ float sigmoidf(float x){
    return 1.f / (1.f + __expf(-x));
}

// ---------------------------------------------------------------------------
// Kernel 1: q/v/k = half(sigmoid(x @ W)). 128x256 tile/CTA, 512 thr = 16 warps
// = 8 rowgroups x 2 column halves; warp: 16 rows x 128 cols (acc 64 regs).
// ---------------------------------------------------------------------------
__global__ __launch_bounds__(512, 1) void proj_kernel(
    const float* __restrict__ x,  const float* __restrict__ Wq,
    const float* __restrict__ Wv, const float* __restrict__ Wk)
{
    extern __shared__ __half smh[];
    __half* Xs = smh;                // 128 x XS2
    __half* Ws = smh + 128 * XS2;    // 128 x WS2 (rows = f, cols = u)

    const int tid = threadIdx.x, w = tid >> 5, lane = tid & 31;
    const int g = lane >> 2, q = lane & 3;
    const int grp = w >> 1, h = w & 1;
    const int tr = lane & 7, sel = lane >> 3;
    const int rb = blockIdx.x * 128, z = blockIdx.y;
    const float* W = (z == 0) ? Wq : (z == 1) ? Wv : Wk;
    __half* Out = (z == 0) ? g_q : (z == 1) ? g_v : g_k;

    #pragma unroll
    for (int i = 0; i < 8; i++){
        int idx = tid + i * 512; int r = idx >> 5, c4 = idx & 31;
        float4 v = *(const float4*)&x[(size_t)(rb + r) * NF + c4 * 4];
        uint2 st; st.x = packh2(v.x, v.y); st.y = packh2(v.z, v.w);
        *(uint2*)&Xs[r * XS2 + c4 * 4] = st;
    }
    #pragma unroll
    for (int i = 0; i < 16; i++){
        int idx = tid + i * 512; int r = idx >> 6, c4 = idx & 63;
        float4 v = *(const float4*)&W[(size_t)r * NU + c4 * 4];
        uint2 st; st.x = packh2(v.x, v.y); st.y = packh2(v.z, v.w);
        *(uint2*)&Ws[r * WS2 + c4 * 4] = st;
    }
    __syncthreads();

    float acc[16][4];
    #pragma unroll
    for (int e = 0; e < 16; e++)
        #pragma unroll
        for (int k = 0; k < 4; k++) acc[e][k] = 0.f;

    // A-frag (X, non-trans): rows grp*16 + (sel&1)*8+tr, col (sel>>1)*8
    uint32_t xaddr = sptr(Xs) + ((grp*16 + (sel&1)*8 + tr) * XS2 + (sel>>1)*8) * 2;
    // B-frag (W, trans): rows f=(sel&1)*8+tr, col u = h*128 + (sel>>1)*8
    uint32_t waddr = sptr(Ws) + (((sel&1)*8 + tr) * WS2 + h*128 + (sel>>1)*8) * 2;

    #pragma unroll
    for (int kb = 0; kb < 8; kb++){
        uint32_t A[4]; ldsm4(A, xaddr + kb * 32);
        #pragma unroll
        for (int ub = 0; ub < 8; ub++){
            uint32_t Bv[4]; ldsm4t(Bv, waddr + kb * 16 * WS2 * 2 + ub * 32);
            hmma(acc[ub*2],     A, Bv[0], Bv[1]);
            hmma(acc[ub*2 + 1], A, Bv[2], Bv[3]);
        }
    }

    const int r0 = rb + grp * 16 + g, r1 = r0 + 8;
    #pragma unroll
    for (int e = 0; e < 16; e++){
        int c = h*128 + (e >> 1)*16 + (e & 1)*8 + 2*q;
        uint32_t lo = packh2(sigmoidf(acc[e][0]), sigmoidf(acc[e][1]));
        uint32_t hi = packh2(sigmoidf(acc[e][2]), sigmoidf(acc[e][3]));
        *(uint32_t*)&Out[(size_t)r0 * NU + c] = lo;
        *(uint32_t*)&Out[(size_t)r1 * NU + c] = hi;
    }
}

// ---------------------------------------------------------------------------
// Kernel 2: flash attention, fp16 HMMA + ldmatrix. Softmax uses a SHIFTED
// static max: p' = exp2(dot*C1 - (C2 - 20)). Shift cancels in O/l exactly.
// q,v in (0,1) => dot in [0,256] => p' in [2^-12.64, 2^20): no fp16 denormals
// (1.6e-4 > min normal 6.1e-5) and no overflow (dot>224.6 unreachable).
// 512 thr = 8 rowgroups x 2 halves; warp: full S 16x64 (dup), half O 16x128.
// ---------------------------------------------------------------------------
__global__ __launch_bounds__(512, 1) void attn_kernel(float* __restrict__ out)
{
    extern __shared__ __half smh[];
    __half* Qs = smh;               // 128 x QS2
    __half* Vs = smh + 128 * QS2;   // 64 x VS2
    __half* Ks = Vs + 64 * VS2;     // 64 x VS2

    const int tid = threadIdx.x, w = tid >> 5, lane = tid & 31;
    const int g = lane >> 2, q = lane & 3;
    const int grp = w >> 1, h = w & 1;
    const int tr = lane & 7, sel = lane >> 3;
    const int qt = 15 - (int)blockIdx.x;      // big tiles first
    const int b  = blockIdx.y;
    const int t0 = qt * 128;
    const int srow0 = t0 + grp * 16 + g, srow1 = srow0 + 8;

    const __half* qb = g_q + (size_t)(b * NT) * NU;
    const __half* vb = g_v + (size_t)(b * NT) * NU;
    const __half* kb = g_k + (size_t)(b * NT) * NU;

    #pragma unroll
    for (int i = 0; i < 8; i++){
        int idx = tid + i * 512; int r = idx >> 5, c8 = idx & 31;
        *(uint4*)&Qs[r * QS2 + c8 * 8] =
            *(const uint4*)&qb[(size_t)(t0 + r) * NU + c8 * 8];
    }

    float oacc[16][4];
    #pragma unroll
    for (int e = 0; e < 16; e++)
        #pragma unroll
        for (int k = 0; k < 4; k++) oacc[e][k] = 0.f;
    float l0 = 0.f, l1 = 0.f;

    // A-frag (Q, non-trans)
    uint32_t qaddr = sptr(Qs) + ((grp*16 + (sel&1)*8 + tr) * QS2 + (sel>>1)*8) * 2;
    // B-frag (V, non-trans): rows s = (sel>>1)*8+tr, col k = (sel&1)*8
    uint32_t vaddr = sptr(Vs) + (((sel>>1)*8 + tr) * VS2 + (sel&1)*8) * 2;
    // B-frag (K, trans): rows s = (sel&1)*8+tr, col u = h*128 + (sel>>1)*8
    uint32_t kaddr = sptr(Ks) + (((sel&1)*8 + tr) * VS2 + h*128 + (sel>>1)*8) * 2;

    const float C1 = 0.127517906167328651f;   // (1/sqrt(128)) * log2(e)
    const float C2 = 12.6444645f;             // 22.627417*log2(e) - 20 (shifted)

    const int jn = 2 * qt + 2;
    for (int j = 0; j < jn; j++){
        const int s0 = j * 64;
        __syncthreads();                       // prev iter S/O MMAs done with Vs/Ks
        #pragma unroll
        for (int i = 0; i < 4; i++){
            int idx = tid + i * 512; int r = idx >> 5, c8 = idx & 31;
            *(uint4*)&Vs[r * VS2 + c8 * 8] =
                *(const uint4*)&vb[(size_t)(s0 + r) * NU + c8 * 8];
            *(uint4*)&Ks[r * VS2 + c8 * 8] =
                *(const uint4*)&kb[(size_t)(s0 + r) * NU + c8 * 8];
        }
        __syncthreads();

        // ---- S = Q . V^T  (16 x 64, full, duplicated within warp pair) ----
        float sacc[8][4];
        #pragma unroll
        for (int nb = 0; nb < 8; nb++)
            #pragma unroll
            for (int k = 0; k < 4; k++) sacc[nb][k] = 0.f;

        #pragma unroll
        for (int kb2 = 0; kb2 < 16; kb2++){
            uint32_t A[4]; ldsm4(A, qaddr + kb2 * 32);
            #pragma unroll
            for (int sb = 0; sb < 4; sb++){
                uint32_t Bv[4]; ldsm4(Bv, vaddr + sb * 16 * VS2 * 2 + kb2 * 32);
                hmma(sacc[sb*2],     A, Bv[0], Bv[1]);
                hmma(sacc[sb*2 + 1], A, Bv[2], Bv[3]);
            }
        }

        // ---- softmax (shifted static max), causal mask ----
        float pl0 = 0.f, pl1 = 0.f;
        #pragma unroll
        for (int nb = 0; nb < 8; nb++){
            int c0 = s0 + nb * 8 + 2 * q;
            float p0 = (c0     < srow0) ? ex2(fmaf(sacc[nb][0], C1, -C2)) : 0.f;
            float p1 = (c0 + 1 < srow0) ? ex2(fmaf(sacc[nb][1], C1, -C2)) : 0.f;
            float p2 = (c0     < srow1) ? ex2(fmaf(sacc[nb][2], C1, -C2)) : 0.f;
            float p3 = (c0 + 1 < srow1) ? ex2(fmaf(sacc[nb][3], C1, -C2)) : 0.f;
            pl0 += p0 + p1; pl1 += p2 + p3;
            sacc[nb][0] = p0; sacc[nb][1] = p1;
            sacc[nb][2] = p2; sacc[nb][3] = p3;
        }
        pl0 += __shfl_xor_sync(~0u, pl0, 1); pl0 += __shfl_xor_sync(~0u, pl0, 2);
        pl1 += __shfl_xor_sync(~0u, pl1, 1); pl1 += __shfl_xor_sync(~0u, pl1, 2);
        l0 += pl0; l1 += pl1;

        // ---- O(16x128) += P . K ; P A-frag = packed C-frag pairs ----
        #pragma unroll
        for (int kc = 0; kc < 4; kc++){
            uint32_t P[4];
            P[0] = packh2(sacc[2*kc][0],   sacc[2*kc][1]);
            P[1] = packh2(sacc[2*kc][2],   sacc[2*kc][3]);
            P[2] = packh2(sacc[2*kc+1][0], sacc[2*kc+1][1]);
            P[3] = packh2(sacc[2*kc+1][2], sacc[2*kc+1][3]);
            #pragma unroll
            for (int ub = 0; ub < 8; ub++){
                uint32_t Bv[4]; ldsm4t(Bv, kaddr + kc * 16 * VS2 * 2 + ub * 32);
                hmma(oacc[ub*2],     P, Bv[0], Bv[1]);
                hmma(oacc[ub*2 + 1], P, Bv[2], Bv[3]);
            }
        }
    }

    // ---- epilogue: normalize; row t==0 forced to zeros ----
    const float inv0 = (srow0 == 0) ? 0.f : 1.f / l0;
    const float inv1 = 1.f / l1;
    float* o0 = out + ((size_t)b * NT + srow0) * NU;
    float* o1 = out + ((size_t)b * NT + srow1) * NU;
    #pragma unroll
    for (int e = 0; e < 16; e++){
        int c = h*128 + (e >> 1)*16 + (e & 1)*8 + 2*q;
        float2 v0, v1;
        v0.x = oacc[e][0] * inv0; v0.y = oacc[e][1] * inv0;
        v1.x = oacc[e][2] * inv1; v1.y = oacc[e][3] * inv1;
        *(float2*)&o0[c] = v0;
        *(float2*)&o1[c] = v1;
    }
}

// ---------------------------------------------------------------------------
extern "C" void kernel_launch(void* const* d_in, const int* in_sizes, int n_in,
                              void* d_out, int out_size)
{
    const float* x  = (const float*)d_in[0];
    const float* Wq = (const float*)d_in[1];
    const float* Wv = (const float*)d_in[2];
    const float* Wk = (const float*)d_in[3];
    float* out = (float*)d_out;

    const int smem1 = (128 * XS2 + 128 * WS2) * 2;          // 102,400 B
    const int smem2 = (128 * QS2 + 2 * 64 * VS2) * 2;       // 135,168 B
    cudaFuncSetAttribute(proj_kernel, cudaFuncAttributeMaxDynamicSharedMemorySize, smem1);
    cudaFuncSetAttribute(attn_kernel, cudaFuncAttributeMaxDynamicSharedMemorySize, smem2);

    proj_kernel<<<dim3(NBT / 128, 3), 512, smem1>>>(x, Wq, Wv, Wk);
    attn_kernel<<<dim3(16, 16), 512, smem2>>>(out);
}

// round 8
// speedup vs baseline: 2.7606x; 1.0331x over previous
#include <cuda_runtime.h>
#include <cuda_fp16.h>
#include <stdint.h>

#define NBAT 16
#define NT 2048
#define NF 128
#define NU 256
#define NBT (NBAT*NT)

__device__ __half g_q[NBT*NU];
__device__ __half g_v[NBT*NU];
__device__ __half g_k[NBT*NU];

#define XS2 136   // proj X tile stride in halves
#define WS2 264   // proj W tile stride
#define QS2 264   // attn Q stride
#define VS2 264   // attn V/K stride

__device__ __forceinline__ uint32_t sptr(const void* p){
    return (uint32_t)__cvta_generic_to_shared(p);
}
__device__ __forceinline__ void ldsm4(uint32_t* d, uint32_t a){
    asm volatile("ldmatrix.sync.aligned.m8n8.x4.shared.b16 {%0,%1,%2,%3}, [%4];"
        : "=r"(d[0]),"=r"(d[1]),"=r"(d[2]),"=r"(d[3]) : "r"(a));
}
__device__ __forceinline__ void ldsm4t(uint32_t* d, uint32_t a){
    asm volatile("ldmatrix.sync.aligned.m8n8.x4.trans.shared.b16 {%0,%1,%2,%3}, [%4];"
        : "=r"(d[0]),"=r"(d[1]),"=r"(d[2]),"=r"(d[3]) : "r"(a));
}
__device__ __forceinline__ void hmma(float* d, const uint32_t* A, uint32_t b0, uint32_t b1){
    asm volatile("mma.sync.aligned.m16n8k16.row.col.f32.f16.f16.f32 "
        "{%0,%1,%2,%3}, {%4,%5,%6,%7}, {%8,%9}, {%0,%1,%2,%3};"
        : "+f"(d[0]),"+f"(d[1]),"+f"(d[2]),"+f"(d[3])
        : "r"(A[0]),"r"(A[1]),"r"(A[2]),"r"(A[3]), "r"(b0),"r"(b1));
}
__device__ __forceinline__ uint32_t packh2(float lo, float hi){
    uint32_t r; asm("cvt.rn.f16x2.f32 %0, %1, %2;" : "=r"(r) : "f"(hi), "f"(lo));
    return r;
}
__device__ __forceinline__ float ex2(float x){
    float r; asm("ex2.approx.f32 %0, %1;" : "=f"(r) : "f"(x)); return r;
}
__device__ __forceinline__ float sigmoidf(float x){
    return 1.f / (1.f + __expf(-x));
}
#define CPA(dst, src) asm volatile("cp.async.cg.shared.global [%0], [%1], 16;" \
    :: "r"(dst), "l"(src))
#define CPC() asm volatile("cp.async.commit_group;" ::: "memory")
#define CPW1() asm volatile("cp.async.wait_group 1;" ::: "memory")

// ---------------------------------------------------------------------------
// Kernel 1: q/v/k = half(sigmoid(x @ W)). 128x256 tile/CTA, 512 thr.
// ---------------------------------------------------------------------------
__global__ __launch_bounds__(512, 1) void proj_kernel(
    const float* __restrict__ x,  const float* __restrict__ Wq,
    const float* __restrict__ Wv, const float* __restrict__ Wk)
{
    extern __shared__ __half smh[];
    __half* Xs = smh;                // 128 x XS2
    __half* Ws = smh + 128 * XS2;    // 128 x WS2 (rows = f, cols = u)

    const int tid = threadIdx.x, w = tid >> 5, lane = tid & 31;
    const int g = lane >> 2, q = lane & 3;
    const int grp = w >> 1, h = w & 1;
    const int tr = lane & 7, sel = lane >> 3;
    const int rb = blockIdx.x * 128, z = blockIdx.y;
    const float* W = (z == 0) ? Wq : (z == 1) ? Wv : Wk;
    __half* Out = (z == 0) ? g_q : (z == 1) ? g_v : g_k;

    #pragma unroll
    for (int i = 0; i < 8; i++){
        int idx = tid + i * 512; int r = idx >> 5, c4 = idx & 31;
        float4 v = *(const float4*)&x[(size_t)(rb + r) * NF + c4 * 4];
        uint2 st; st.x = packh2(v.x, v.y); st.y = packh2(v.z, v.w);
        *(uint2*)&Xs[r * XS2 + c4 * 4] = st;
    }
    #pragma unroll
    for (int i = 0; i < 16; i++){
        int idx = tid + i * 512; int r = idx >> 6, c4 = idx & 63;
        float4 v = *(const float4*)&W[(size_t)r * NU + c4 * 4];
        uint2 st; st.x = packh2(v.x, v.y); st.y = packh2(v.z, v.w);
        *(uint2*)&Ws[r * WS2 + c4 * 4] = st;
    }
    __syncthreads();

    float acc[16][4];
    #pragma unroll
    for (int e = 0; e < 16; e++)
        #pragma unroll
        for (int k = 0; k < 4; k++) acc[e][k] = 0.f;

    uint32_t xaddr = sptr(Xs) + ((grp*16 + (sel&1)*8 + tr) * XS2 + (sel>>1)*8) * 2;
    uint32_t waddr = sptr(Ws) + (((sel&1)*8 + tr) * WS2 + h*128 + (sel>>1)*8) * 2;

    #pragma unroll
    for (int kb = 0; kb < 8; kb++){
        uint32_t A[4]; ldsm4(A, xaddr + kb * 32);
        #pragma unroll
        for (int ub = 0; ub < 8; ub++){
            uint32_t Bv[4]; ldsm4t(Bv, waddr + kb * 16 * WS2 * 2 + ub * 32);
            hmma(acc[ub*2],     A, Bv[0], Bv[1]);
            hmma(acc[ub*2 + 1], A, Bv[2], Bv[3]);
        }
    }

    const int r0 = rb + grp * 16 + g, r1 = r0 + 8;
    #pragma unroll
    for (int e = 0; e < 16; e++){
        int c = h*128 + (e >> 1)*16 + (e & 1)*8 + 2*q;
        uint32_t lo = packh2(sigmoidf(acc[e][0]), sigmoidf(acc[e][1]));
        uint32_t hi = packh2(sigmoidf(acc[e][2]), sigmoidf(acc[e][3]));
        *(uint32_t*)&Out[(size_t)r0 * NU + c] = lo;
        *(uint32_t*)&Out[(size_t)r1 * NU + c] = hi;
    }
}

// ---------------------------------------------------------------------------
// Kernel 2: flash attention, fp16 HMMA + ldmatrix + double-buffered cp.async.
// Shifted static softmax max: p' = exp2(dot*C1 - C2'), C2' = C2 - 20; shift
// cancels in O/l. p' in [2^-12.64, 2^20): no fp16 denormals, no overflow.
// ---------------------------------------------------------------------------
__global__ __launch_bounds__(512, 1) void attn_kernel(float* __restrict__ out)
{
    extern __shared__ __half smh[];
    __half* Qs = smh;                              // 128 x QS2
    const int STG = 2 * 64 * VS2;                  // halves per stage (V+K)
    __half* VK0 = smh + 128 * QS2;                 // stage 0: V | K
    __half* VK1 = VK0 + STG;                       // stage 1

    const int tid = threadIdx.x, w = tid >> 5, lane = tid & 31;
    const int g = lane >> 2, q = lane & 3;
    const int grp = w >> 1, h = w & 1;
    const int tr = lane & 7, sel = lane >> 3;
    const int qt = 15 - (int)blockIdx.x;           // big tiles first
    const int b  = blockIdx.y;
    const int t0 = qt * 128;
    const int srow0 = t0 + grp * 16 + g, srow1 = srow0 + 8;

    const __half* qb = g_q + (size_t)(b * NT) * NU;
    const __half* vb = g_v + (size_t)(b * NT) * NU;
    const __half* kb = g_k + (size_t)(b * NT) * NU;

    #pragma unroll
    for (int i = 0; i < 8; i++){
        int idx = tid + i * 512; int r = idx >> 5, c8 = idx & 31;
        *(uint4*)&Qs[r * QS2 + c8 * 8] =
            *(const uint4*)&qb[(size_t)(t0 + r) * NU + c8 * 8];
    }

    // cp.async per-thread chunk coords: 32 x 16B chunks per 64-row tile slab
    const int cr = tid >> 5;          // row 0..15 base (4 slabs of 16 rows)
    const int cc = tid & 31;          // 16B chunk in row (32 per 512B row)
    uint32_t vdst0 = sptr(VK0) + 0;
    // precomputed ldsm bases per stage
    uint32_t qaddr  = sptr(Qs) + ((grp*16 + (sel&1)*8 + tr) * QS2 + (sel>>1)*8) * 2;
    uint32_t vbase0 = sptr(VK0) + (((sel>>1)*8 + tr) * VS2 + (sel&1)*8) * 2;
    uint32_t kbase0 = sptr(VK0 + 64*VS2) + (((sel&1)*8 + tr) * VS2 + h*128 + (sel>>1)*8) * 2;
    const uint32_t stgB = (uint32_t)STG * 2;       // stage stride in bytes

    // issue copies for tile s0 into stage stg
    auto issue = [&](int s0, int stg){
        uint32_t base = vdst0 + (uint32_t)stg * stgB;
        #pragma unroll
        for (int i = 0; i < 4; i++){
            int r = cr + i * 16;
            uint32_t dv = base + (uint32_t)(r * VS2 * 2 + cc * 16);
            CPA(dv, (const char*)&vb[(size_t)(s0 + r) * NU] + cc * 16);
        }
        uint32_t kb0 = base + (uint32_t)(64 * VS2 * 2);
        #pragma unroll
        for (int i = 0; i < 4; i++){
            int r = cr + i * 16;
            uint32_t dk = kb0 + (uint32_t)(r * VS2 * 2 + cc * 16);
            CPA(dk, (const char*)&kb[(size_t)(s0 + r) * NU] + cc * 16);
        }
    };

    float oacc[16][4];
    #pragma unroll
    for (int e = 0; e < 16; e++)
        #pragma unroll
        for (int k = 0; k < 4; k++) oacc[e][k] = 0.f;
    float l0 = 0.f, l1 = 0.f;

    const float C1 = 0.127517906167328651f;   // (1/sqrt(128)) * log2(e)
    const float C2 = 12.6444645f;             // 22.627417*log2(e) - 20 (shifted)

    const int jn = 2 * qt + 2;
    issue(0, 0); CPC();                        // prologue: tile 0 -> stage 0

    for (int j = 0; j < jn; j++){
        const int s0 = j * 64;
        __syncthreads();                       // all warps done computing j-1
        if (j + 1 < jn) issue((j + 1) * 64, (j + 1) & 1);
        CPC();
        CPW1();                                // tile j landed (own copies)
        __syncthreads();                       // visible to all warps

        const uint32_t soff = (uint32_t)(j & 1) * stgB;
        const uint32_t vaddr = vbase0 + soff;
        const uint32_t kaddr = kbase0 + soff;

        // ---- S = Q . V^T  (16 x 64, duplicated within warp pair) ----
        float sacc[8][4];
        #pragma unroll
        for (int nb = 0; nb < 8; nb++)
            #pragma unroll
            for (int k = 0; k < 4; k++) sacc[nb][k] = 0.f;

        #pragma unroll
        for (int kb2 = 0; kb2 < 16; kb2++){
            uint32_t A[4]; ldsm4(A, qaddr + kb2 * 32);
            #pragma unroll
            for (int sb = 0; sb < 4; sb++){
                uint32_t Bv[4]; ldsm4(Bv, vaddr + sb * 16 * VS2 * 2 + kb2 * 32);
                hmma(sacc[sb*2],     A, Bv[0], Bv[1]);
                hmma(sacc[sb*2 + 1], A, Bv[2], Bv[3]);
            }
        }

        // ---- softmax (shifted static max), causal mask ----
        float pl0 = 0.f, pl1 = 0.f;
        #pragma unroll
        for (int nb = 0; nb < 8; nb++){
            int c0 = s0 + nb * 8 + 2 * q;
            float p0 = (c0     < srow0) ? ex2(fmaf(sacc[nb][0], C1, -C2)) : 0.f;
            float p1 = (c0 + 1 < srow0) ? ex2(fmaf(sacc[nb][1], C1, -C2)) : 0.f;
            float p2 = (c0     < srow1) ? ex2(fmaf(sacc[nb][2], C1, -C2)) : 0.f;
            float p3 = (c0 + 1 < srow1) ? ex2(fmaf(sacc[nb][3], C1, -C2)) : 0.f;
            pl0 += p0 + p1; pl1 += p2 + p3;
            sacc[nb][0] = p0; sacc[nb][1] = p1;
            sacc[nb][2] = p2; sacc[nb][3] = p3;
        }
        pl0 += __shfl_xor_sync(~0u, pl0, 1); pl0 += __shfl_xor_sync(~0u, pl0, 2);
        pl1 += __shfl_xor_sync(~0u, pl1, 1); pl1 += __shfl_xor_sync(~0u, pl1, 2);
        l0 += pl0; l1 += pl1;

        // ---- O(16x128) += P . K ; P A-frag = packed C-frag pairs ----
        #pragma unroll
        for (int kc = 0; kc < 4; kc++){
            uint32_t P[4];
            P[0] = packh2(sacc[2*kc][0],   sacc[2*kc][1]);
            P[1] = packh2(sacc[2*kc][2],   sacc[2*kc][3]);
            P[2] = packh2(sacc[2*kc+1][0], sacc[2*kc+1][1]);
            P[3] = packh2(sacc[2*kc+1][2], sacc[2*kc+1][3]);
            #pragma unroll
            for (int ub = 0; ub < 8; ub++){
                uint32_t Bv[4]; ldsm4t(Bv, kaddr + kc * 16 * VS2 * 2 + ub * 32);
                hmma(oacc[ub*2],     P, Bv[0], Bv[1]);
                hmma(oacc[ub*2 + 1], P, Bv[2], Bv[3]);
            }
        }
    }

    // ---- epilogue: normalize; row t==0 forced to zeros ----
    const float inv0 = (srow0 == 0) ? 0.f : 1.f / l0;
    const float inv1 = 1.f / l1;
    float* o0 = out + ((size_t)b * NT + srow0) * NU;
    float* o1 = out + ((size_t)b * NT + srow1) * NU;
    #pragma unroll
    for (int e = 0; e < 16; e++){
        int c = h*128 + (e >> 1)*16 + (e & 1)*8 + 2*q;
        float2 v0, v1;
        v0.x = oacc[e][0] * inv0; v0.y = oacc[e][1] * inv0;
        v1.x = oacc[e][2] * inv1; v1.y = oacc[e][3] * inv1;
        *(float2*)&o0[c] = v0;
        *(float2*)&o1[c] = v1;
    }
}

// ---------------------------------------------------------------------------
extern "C" void kernel_launch(void* const* d_in, const int* in_sizes, int n_in,
                              void* d_out, int out_size)
{
    const float* x  = (const float*)d_in[0];
    const float* Wq = (const float*)d_in[1];
    const float* Wv = (const float*)d_in[2];
    const float* Wk = (const float*)d_in[3];
    float* out = (float*)d_out;

    const int smem1 = (128 * XS2 + 128 * WS2) * 2;          // 102,400 B
    const int smem2 = (128 * QS2 + 4 * 64 * VS2) * 2;       // 202,752 B
    cudaFuncSetAttribute(proj_kernel, cudaFuncAttributeMaxDynamicSharedMemorySize, smem1);
    cudaFuncSetAttribute(attn_kernel, cudaFuncAttributeMaxDynamicSharedMemorySize, smem2);

    proj_kernel<<<dim3(NBT / 128, 3), 512, smem1>>>(x, Wq, Wv, Wk);
    attn_kernel<<<dim3(16, 16), 512, smem2>>>(out);
}

// round 9
// speedup vs baseline: 3.6718x; 1.3300x over previous
#include <cuda_runtime.h>
#include <cuda_fp16.h>
#include <stdint.h>

#define NBAT 16
#define NT 2048
#define NF 128
#define NU 256
#define NBT (NBAT*NT)

__device__ __half g_q[NBT*NU];
__device__ __half g_v[NBT*NU];
__device__ __half g_k[NBT*NU];

#define XS2 136   // proj X tile stride in halves
#define WS2 264   // proj W tile stride
#define QS2 264   // attn Q stride
#define VS2 264   // attn V/K stride
#define PS2 72    // attn P-exchange stride

__device__ __forceinline__ uint32_t sptr(const void* p){
    return (uint32_t)__cvta_generic_to_shared(p);
}
__device__ __forceinline__ void ldsm4(uint32_t* d, uint32_t a){
    asm volatile("ldmatrix.sync.aligned.m8n8.x4.shared.b16 {%0,%1,%2,%3}, [%4];"
        : "=r"(d[0]),"=r"(d[1]),"=r"(d[2]),"=r"(d[3]) : "r"(a));
}
__device__ __forceinline__ void ldsm4t(uint32_t* d, uint32_t a){
    asm volatile("ldmatrix.sync.aligned.m8n8.x4.trans.shared.b16 {%0,%1,%2,%3}, [%4];"
        : "=r"(d[0]),"=r"(d[1]),"=r"(d[2]),"=r"(d[3]) : "r"(a));
}
__device__ __forceinline__ void hmma(float* d, const uint32_t* A, uint32_t b0, uint32_t b1){
    asm volatile("mma.sync.aligned.m16n8k16.row.col.f32.f16.f16.f32 "
        "{%0,%1,%2,%3}, {%4,%5,%6,%7}, {%8,%9}, {%0,%1,%2,%3};"
        : "+f"(d[0]),"+f"(d[1]),"+f"(d[2]),"+f"(d[3])
        : "r"(A[0]),"r"(A[1]),"r"(A[2]),"r"(A[3]), "r"(b0),"r"(b1));
}
__device__ __forceinline__ uint32_t packh2(float lo, float hi){
    uint32_t r; asm("cvt.rn.f16x2.f32 %0, %1, %2;" : "=r"(r) : "f"(hi), "f"(lo));
    return r;
}
__device__ __forceinline__ float ex2(float x){
    float r; asm("ex2.approx.f32 %0, %1;" : "=f"(r) : "f"(x)); return r;
}
__device__ __forceinline__ float sigmoidf(float x){
    return 1.f / (1.f + __expf(-x));
}
#define CPA(dst, src) asm volatile("cp.async.cg.shared.global [%0], [%1], 16;" \
    :: "r"(dst), "l"(src))
#define CPC() asm volatile("cp.async.commit_group;" ::: "memory")
#define CPW0() asm volatile("cp.async.wait_group 0;" ::: "memory")

// ---------------------------------------------------------------------------
// Kernel 1: q/v/k = half(sigmoid(x @ W)). 128x256 tile/CTA, 512 thr.
// ---------------------------------------------------------------------------
__global__ __launch_bounds__(512, 1) void proj_kernel(
    const float* __restrict__ x,  const float* __restrict__ Wq,
    const float* __restrict__ Wv, const float* __restrict__ Wk)
{
    extern __shared__ __half smh[];
    __half* Xs = smh;                // 128 x XS2
    __half* Ws = smh + 128 * XS2;    // 128 x WS2 (rows = f, cols = u)

    const int tid = threadIdx.x, w = tid >> 5, lane = tid & 31;
    const int g = lane >> 2, q = lane & 3;
    const int grp = w >> 1, h = w & 1;
    const int tr = lane & 7, sel = lane >> 3;
    const int rb = blockIdx.x * 128, z = blockIdx.y;
    const float* W = (z == 0) ? Wq : (z == 1) ? Wv : Wk;
    __half* Out = (z == 0) ? g_q : (z == 1) ? g_v : g_k;

    #pragma unroll
    for (int i = 0; i < 8; i++){
        int idx = tid + i * 512; int r = idx >> 5, c4 = idx & 31;
        float4 v = *(const float4*)&x[(size_t)(rb + r) * NF + c4 * 4];
        uint2 st; st.x = packh2(v.x, v.y); st.y = packh2(v.z, v.w);
        *(uint2*)&Xs[r * XS2 + c4 * 4] = st;
    }
    #pragma unroll
    for (int i = 0; i < 16; i++){
        int idx = tid + i * 512; int r = idx >> 6, c4 = idx & 63;
        float4 v = *(const float4*)&W[(size_t)r * NU + c4 * 4];
        uint2 st; st.x = packh2(v.x, v.y); st.y = packh2(v.z, v.w);
        *(uint2*)&Ws[r * WS2 + c4 * 4] = st;
    }
    __syncthreads();

    float acc[16][4];
    #pragma unroll
    for (int e = 0; e < 16; e++)
        #pragma unroll
        for (int k = 0; k < 4; k++) acc[e][k] = 0.f;

    uint32_t xaddr = sptr(Xs) + ((grp*16 + (sel&1)*8 + tr) * XS2 + (sel>>1)*8) * 2;
    uint32_t waddr = sptr(Ws) + (((sel&1)*8 + tr) * WS2 + h*128 + (sel>>1)*8) * 2;

    #pragma unroll
    for (int kb = 0; kb < 8; kb++){
        uint32_t A[4]; ldsm4(A, xaddr + kb * 32);
        #pragma unroll
        for (int ub = 0; ub < 8; ub++){
            uint32_t Bv[4]; ldsm4t(Bv, waddr + kb * 16 * WS2 * 2 + ub * 32);
            hmma(acc[ub*2],     A, Bv[0], Bv[1]);
            hmma(acc[ub*2 + 1], A, Bv[2], Bv[3]);
        }
    }

    const int r0 = rb + grp * 16 + g, r1 = r0 + 8;
    #pragma unroll
    for (int e = 0; e < 16; e++){
        int c = h*128 + (e >> 1)*16 + (e & 1)*8 + 2*q;
        uint32_t lo = packh2(sigmoidf(acc[e][0]), sigmoidf(acc[e][1]));
        uint32_t hi = packh2(sigmoidf(acc[e][2]), sigmoidf(acc[e][3]));
        *(uint32_t*)&Out[(size_t)r0 * NU + c] = lo;
        *(uint32_t*)&Out[(size_t)r1 * NU + c] = hi;
    }
}

// ---------------------------------------------------------------------------
// Kernel 2: flash attention. 64-query tiles, 256 thr, 2 CTAs/SM (latency
// hiding across CTAs). 8 warps = 4 rowgroups x 2 halves. Warp computes HALF
// of S (16x32); full P recovered via smem exchange (no duplicated S-MMA).
// Shifted static softmax max: p' = exp2(dot*C1 - C2'); shift cancels in O/l.
// ---------------------------------------------------------------------------
__global__ __launch_bounds__(256, 2) void attn_kernel(float* __restrict__ out)
{
    extern __shared__ __half smh[];
    __half* Qs = smh;                       // 64 x QS2
    __half* Vs = smh + 64 * QS2;            // 64 x VS2
    __half* Ks = Vs + 64 * VS2;             // 64 x VS2
    __half* Ps = Ks + 64 * VS2;             // 64 x PS2
    float*  Ls = (float*)(Ps + 64 * PS2);   // 64 x 2 row-sum partials

    const int tid = threadIdx.x, w = tid >> 5, lane = tid & 31;
    const int g = lane >> 2, q = lane & 3;
    const int grp = w >> 1, h = w & 1;
    const int tr = lane & 7, sel = lane >> 3;
    const int qt = 31 - (int)blockIdx.x;    // big tiles first
    const int b  = blockIdx.y;
    const int t0 = qt * 64;
    const int lrow = grp * 16 + g;
    const int srow0 = t0 + lrow, srow1 = srow0 + 8;

    const __half* qb = g_q + (size_t)(b * NT) * NU;
    const __half* vb = g_v + (size_t)(b * NT) * NU;
    const __half* kb = g_k + (size_t)(b * NT) * NU;

    // cp.async chunk coords: 64 rows x 32 x 16B chunks, 8 per thread
    const int cr = tid >> 5, cc = tid & 31;
    const uint32_t vdst = sptr(Vs), kdst = sptr(Ks);
    auto issueV = [&](int s0){
        #pragma unroll
        for (int i = 0; i < 8; i++){
            int r = cr + i * 8;
            CPA(vdst + (uint32_t)(r * VS2 * 2 + cc * 16),
                (const char*)&vb[(size_t)(s0 + r) * NU] + cc * 16);
        }
    };
    auto issueK = [&](int s0){
        #pragma unroll
        for (int i = 0; i < 8; i++){
            int r = cr + i * 8;
            CPA(kdst + (uint32_t)(r * VS2 * 2 + cc * 16),
                (const char*)&kb[(size_t)(s0 + r) * NU] + cc * 16);
        }
    };

    issueV(0); issueK(0); CPC();            // prologue: tile 0 in flight

    #pragma unroll
    for (int i = 0; i < 8; i++){            // Q tile 64 x 256 (overlaps copies)
        int idx = tid + i * 256; int r = idx >> 5, c8 = idx & 31;
        *(uint4*)&Qs[r * QS2 + c8 * 8] =
            *(const uint4*)&qb[(size_t)(t0 + r) * NU + c8 * 8];
    }

    float oacc[16][4];
    #pragma unroll
    for (int e = 0; e < 16; e++)
        #pragma unroll
        for (int k = 0; k < 4; k++) oacc[e][k] = 0.f;
    float l0 = 0.f, l1 = 0.f;

    uint32_t qaddr = sptr(Qs) + ((lrow - g + (sel&1)*8 + tr) * QS2 + (sel>>1)*8) * 2;
    uint32_t vaddr = vdst + ((h*32 + (sel>>1)*8 + tr) * VS2 + (sel&1)*8) * 2;
    uint32_t kaddr = kdst + (((sel&1)*8 + tr) * VS2 + h*128 + (sel>>1)*8) * 2;
    uint32_t paddr = sptr(Ps) + ((grp*16 + (sel&1)*8 + tr) * PS2 + (sel>>1)*8) * 2;

    const float C1 = 0.127517906167328651f;   // (1/sqrt(128)) * log2(e)
    const float C2 = 12.6444645f;             // 22.627417*log2(e) - 20 (shifted)

    const int jn = qt + 1;
    for (int j = 0; j < jn; j++){
        const int s0 = j * 64;
        CPW0();
        __syncthreads();                      // tile j visible to all warps

        // ---- S half: 16 rows x 32 cols (cols h*32..h*32+31) ----
        float sacc[4][4];
        #pragma unroll
        for (int nb = 0; nb < 4; nb++)
            #pragma unroll
            for (int k = 0; k < 4; k++) sacc[nb][k] = 0.f;

        #pragma unroll
        for (int kb2 = 0; kb2 < 16; kb2++){
            uint32_t A[4]; ldsm4(A, qaddr + kb2 * 32);
            #pragma unroll
            for (int sb = 0; sb < 2; sb++){
                uint32_t Bv[4]; ldsm4(Bv, vaddr + sb * 16 * VS2 * 2 + kb2 * 32);
                hmma(sacc[sb*2],     A, Bv[0], Bv[1]);
                hmma(sacc[sb*2 + 1], A, Bv[2], Bv[3]);
            }
        }

        // ---- softmax (shifted static max) + P/L exchange ----
        float pl0 = 0.f, pl1 = 0.f;
        #pragma unroll
        for (int nb = 0; nb < 4; nb++){
            int c0 = s0 + h*32 + nb*8 + 2*q;
            float p0 = (c0     < srow0) ? ex2(fmaf(sacc[nb][0], C1, -C2)) : 0.f;
            float p1 = (c0 + 1 < srow0) ? ex2(fmaf(sacc[nb][1], C1, -C2)) : 0.f;
            float p2 = (c0     < srow1) ? ex2(fmaf(sacc[nb][2], C1, -C2)) : 0.f;
            float p3 = (c0 + 1 < srow1) ? ex2(fmaf(sacc[nb][3], C1, -C2)) : 0.f;
            pl0 += p0 + p1; pl1 += p2 + p3;
            int col = h*32 + nb*8 + 2*q;
            *(uint32_t*)&Ps[lrow * PS2 + col]       = packh2(p0, p1);
            *(uint32_t*)&Ps[(lrow + 8) * PS2 + col] = packh2(p2, p3);
        }
        pl0 += __shfl_xor_sync(~0u, pl0, 1); pl0 += __shfl_xor_sync(~0u, pl0, 2);
        pl1 += __shfl_xor_sync(~0u, pl1, 1); pl1 += __shfl_xor_sync(~0u, pl1, 2);
        if (q == 0){
            Ls[lrow * 2 + h]       = pl0;
            Ls[(lrow + 8) * 2 + h] = pl1;
        }
        __syncthreads();                      // P/L ready; V fully consumed

        if (j + 1 < jn) issueV((j + 1) * 64); // overlap V(j+1) with O-GEMM

        l0 += Ls[lrow * 2] + Ls[lrow * 2 + 1];
        l1 += Ls[(lrow + 8) * 2] + Ls[(lrow + 8) * 2 + 1];

        // ---- O(16x128) += P . K ; P read back as A-frags ----
        #pragma unroll
        for (int kc = 0; kc < 4; kc++){
            uint32_t P[4]; ldsm4(P, paddr + kc * 32);
            #pragma unroll
            for (int ub = 0; ub < 8; ub++){
                uint32_t Bv[4]; ldsm4t(Bv, kaddr + kc * 16 * VS2 * 2 + ub * 32);
                hmma(oacc[ub*2],     P, Bv[0], Bv[1]);
                hmma(oacc[ub*2 + 1], P, Bv[2], Bv[3]);
            }
        }
        __syncthreads();                      // all done with Ks/Ps
        if (j + 1 < jn){ issueK((j + 1) * 64); CPC(); }
    }

    // ---- epilogue: normalize; row t==0 forced to zeros ----
    const float inv0 = (srow0 == 0) ? 0.f : 1.f / l0;
    const float inv1 = 1.f / l1;
    float* o0 = out + ((size_t)b * NT + srow0) * NU;
    float* o1 = out + ((size_t)b * NT + srow1) * NU;
    #pragma unroll
    for (int e = 0; e < 16; e++){
        int c = h*128 + (e >> 1)*16 + (e & 1)*8 + 2*q;
        float2 v0, v1;
        v0.x = oacc[e][0] * inv0; v0.y = oacc[e][1] * inv0;
        v1.x = oacc[e][2] * inv1; v1.y = oacc[e][3] * inv1;
        *(float2*)&o0[c] = v0;
        *(float2*)&o1[c] = v1;
    }
}

// ---------------------------------------------------------------------------
extern "C" void kernel_launch(void* const* d_in, const int* in_sizes, int n_in,
                              void* d_out, int out_size)
{
    const float* x  = (const float*)d_in[0];
    const float* Wq = (const float*)d_in[1];
    const float* Wv = (const float*)d_in[2];
    const float* Wk = (const float*)d_in[3];
    float* out = (float*)d_out;

    const int smem1 = (128 * XS2 + 128 * WS2) * 2;                       // 102,400 B
    const int smem2 = (64*QS2 + 2*64*VS2 + 64*PS2) * 2 + 64 * 2 * 4;     // 111,104 B
    cudaFuncSetAttribute(proj_kernel, cudaFuncAttributeMaxDynamicSharedMemorySize, smem1);
    cudaFuncSetAttribute(attn_kernel, cudaFuncAttributeMaxDynamicSharedMemorySize, smem2);

    proj_kernel<<<dim3(NBT / 128, 3), 512, smem1>>>(x, Wq, Wv, Wk);
    attn_kernel<<<dim3(32, 16), 256, smem2>>>(out);
}

// round 11
// speedup vs baseline: 3.7763x; 1.0285x over previous
#include <cuda_runtime.h>
#include <cuda_fp16.h>
#include <stdint.h>

#define NBAT 16
#define NT 2048
#define NF 128
#define NU 256
#define NBT (NBAT*NT)

__device__ __half g_q[NBT*NU];
__device__ __half g_v[NBT*NU];
__device__ __half g_k[NBT*NU];

#define XS2 136   // proj X tile stride in halves
#define WS2 264   // proj W tile stride
#define QS2 264   // attn Q stride
#define VS2 264   // attn V/K stride
#define PS2 72    // attn P-exchange stride

__device__ __forceinline__ uint32_t sptr(const void* p){
    return (uint32_t)__cvta_generic_to_shared(p);
}
__device__ __forceinline__ void ldsm4(uint32_t* d, uint32_t a){
    asm volatile("ldmatrix.sync.aligned.m8n8.x4.shared.b16 {%0,%1,%2,%3}, [%4];"
        : "=r"(d[0]),"=r"(d[1]),"=r"(d[2]),"=r"(d[3]) : "r"(a));
}
__device__ __forceinline__ void ldsm4t(uint32_t* d, uint32_t a){
    asm volatile("ldmatrix.sync.aligned.m8n8.x4.trans.shared.b16 {%0,%1,%2,%3}, [%4];"
        : "=r"(d[0]),"=r"(d[1]),"=r"(d[2]),"=r"(d[3]) : "r"(a));
}
__device__ __forceinline__ void hmma(float* d, const uint32_t* A, uint32_t b0, uint32_t b1){
    asm volatile("mma.sync.aligned.m16n8k16.row.col.f32.f16.f16.f32 "
        "{%0,%1,%2,%3}, {%4,%5,%6,%7}, {%8,%9}, {%0,%1,%2,%3};"
        : "+f"(d[0]),"+f"(d[1]),"+f"(d[2]),"+f"(d[3])
        : "r"(A[0]),"r"(A[1]),"r"(A[2]),"r"(A[3]), "r"(b0),"r"(b1));
}
__device__ __forceinline__ uint32_t packh2(float lo, float hi){
    uint32_t r; asm("cvt.rn.f16x2.f32 %0, %1, %2;" : "=r"(r) : "f"(hi), "f"(lo));
    return r;
}
__device__ __forceinline__ float ex2(float x){
    float r; asm("ex2.approx.f32 %0, %1;" : "=f"(r) : "f"(x)); return r;
}
__device__ __forceinline__ float sigmoidf(float x){
    return 1.f / (1.f + __expf(-x));
}
#define CPA(dst, src) asm volatile("cp.async.cg.shared.global [%0], [%1], 16;" \
    :: "r"(dst), "l"(src))
#define CPC() asm volatile("cp.async.commit_group;" ::: "memory")
#define CPW0() asm volatile("cp.async.wait_group 0;" ::: "memory")
#define CPW1() asm volatile("cp.async.wait_group 1;" ::: "memory")

// ---------------------------------------------------------------------------
// Kernel 1: q/v/k = half(sigmoid(x @ W)). 128x256 tile/CTA, 512 thr.
// ---------------------------------------------------------------------------
__global__ __launch_bounds__(512, 1) void proj_kernel(
    const float* __restrict__ x,  const float* __restrict__ Wq,
    const float* __restrict__ Wv, const float* __restrict__ Wk)
{
    extern __shared__ __half smh[];
    __half* Xs = smh;                // 128 x XS2
    __half* Ws = smh + 128 * XS2;    // 128 x WS2 (rows = f, cols = u)

    const int tid = threadIdx.x, w = tid >> 5, lane = tid & 31;
    const int g = lane >> 2, q = lane & 3;
    const int grp = w >> 1, h = w & 1;
    const int tr = lane & 7, sel = lane >> 3;
    const int rb = blockIdx.x * 128, z = blockIdx.y;
    const float* W = (z == 0) ? Wq : (z == 1) ? Wv : Wk;
    __half* Out = (z == 0) ? g_q : (z == 1) ? g_v : g_k;

    #pragma unroll
    for (int i = 0; i < 8; i++){
        int idx = tid + i * 512; int r = idx >> 5, c4 = idx & 31;
        float4 v = *(const float4*)&x[(size_t)(rb + r) * NF + c4 * 4];
        uint2 st; st.x = packh2(v.x, v.y); st.y = packh2(v.z, v.w);
        *(uint2*)&Xs[r * XS2 + c4 * 4] = st;
    }
    #pragma unroll
    for (int i = 0; i < 16; i++){
        int idx = tid + i * 512; int r = idx >> 6, c4 = idx & 63;
        float4 v = *(const float4*)&W[(size_t)r * NU + c4 * 4];
        uint2 st; st.x = packh2(v.x, v.y); st.y = packh2(v.z, v.w);
        *(uint2*)&Ws[r * WS2 + c4 * 4] = st;
    }
    __syncthreads();

    float acc[16][4];
    #pragma unroll
    for (int e = 0; e < 16; e++)
        #pragma unroll
        for (int k = 0; k < 4; k++) acc[e][k] = 0.f;

    uint32_t xaddr = sptr(Xs) + ((grp*16 + (sel&1)*8 + tr) * XS2 + (sel>>1)*8) * 2;
    uint32_t waddr = sptr(Ws) + (((sel&1)*8 + tr) * WS2 + h*128 + (sel>>1)*8) * 2;

    #pragma unroll
    for (int kb = 0; kb < 8; kb++){
        uint32_t A[4]; ldsm4(A, xaddr + kb * 32);
        #pragma unroll
        for (int ub = 0; ub < 8; ub++){
            uint32_t Bv[4]; ldsm4t(Bv, waddr + kb * 16 * WS2 * 2 + ub * 32);
            hmma(acc[ub*2],     A, Bv[0], Bv[1]);
            hmma(acc[ub*2 + 1], A, Bv[2], Bv[3]);
        }
    }

    const int r0 = rb + grp * 16 + g, r1 = r0 + 8;
    #pragma unroll
    for (int e = 0; e < 16; e++){
        int c = h*128 + (e >> 1)*16 + (e & 1)*8 + 2*q;
        uint32_t lo = packh2(sigmoidf(acc[e][0]), sigmoidf(acc[e][1]));
        uint32_t hi = packh2(sigmoidf(acc[e][2]), sigmoidf(acc[e][3]));
        *(uint32_t*)&Out[(size_t)r0 * NU + c] = lo;
        *(uint32_t*)&Out[(size_t)r1 * NU + c] = hi;
    }
}

// ---------------------------------------------------------------------------
// Kernel 2: flash attention. 64-query tiles, 256 thr, 2 CTAs/SM. Warp computes
// half of S (16x32); full P via smem exchange. V and K are SEPARATE cp.async
// commit groups with selective waits: K(j) hidden behind S+softmax(j), V(j+1)
// hidden behind O(j). Shifted static softmax max cancels in O/l.
// ---------------------------------------------------------------------------
__global__ __launch_bounds__(256, 2) void attn_kernel(float* __restrict__ out)
{
    extern __shared__ __half smh[];
    __half* Qs = smh;                       // 64 x QS2
    __half* Vs = smh + 64 * QS2;            // 64 x VS2
    __half* Ks = Vs + 64 * VS2;             // 64 x VS2
    __half* Ps = Ks + 64 * VS2;             // 64 x PS2
    float*  Ls = (float*)(Ps + 64 * PS2);   // 64 x 2 row-sum partials

    const int tid = threadIdx.x, w = tid >> 5, lane = tid & 31;
    const int g = lane >> 2, q = lane & 3;
    const int grp = w >> 1, h = w & 1;
    const int tr = lane & 7, sel = lane >> 3;
    const int qt = 31 - (int)blockIdx.x;    // big tiles first
    const int b  = blockIdx.y;
    const int t0 = qt * 64;
    const int lrow = grp * 16 + g;
    const int srow0 = t0 + lrow, srow1 = srow0 + 8;

    const __half* qb = g_q + (size_t)(b * NT) * NU;
    const __half* vb = g_v + (size_t)(b * NT) * NU;
    const __half* kb = g_k + (size_t)(b * NT) * NU;

    const int cr = tid >> 5, cc = tid & 31;
    const uint32_t vdst = sptr(Vs), kdst = sptr(Ks);
    auto issueV = [&](int s0){
        #pragma unroll
        for (int i = 0; i < 8; i++){
            int r = cr + i * 8;
            CPA(vdst + (uint32_t)(r * VS2 * 2 + cc * 16),
                (const char*)&vb[(size_t)(s0 + r) * NU] + cc * 16);
        }
    };
    auto issueK = [&](int s0){
        #pragma unroll
        for (int i = 0; i < 8; i++){
            int r = cr + i * 8;
            CPA(kdst + (uint32_t)(r * VS2 * 2 + cc * 16),
                (const char*)&kb[(size_t)(s0 + r) * NU] + cc * 16);
        }
    };

    issueV(0); CPC();                       // group: V(0)
    issueK(0); CPC();                       // group: K(0)

    #pragma unroll
    for (int i = 0; i < 8; i++){            // Q tile 64 x 256 (overlaps copies)
        int idx = tid + i * 256; int r = idx >> 5, c8 = idx & 31;
        *(uint4*)&Qs[r * QS2 + c8 * 8] =
            *(const uint4*)&qb[(size_t)(t0 + r) * NU + c8 * 8];
    }

    float oacc[16][4];
    #pragma unroll
    for (int e = 0; e < 16; e++)
        #pragma unroll
        for (int k = 0; k < 4; k++) oacc[e][k] = 0.f;
    float l0 = 0.f, l1 = 0.f;

    uint32_t qaddr = sptr(Qs) + ((lrow - g + (sel&1)*8 + tr) * QS2 + (sel>>1)*8) * 2;
    uint32_t vaddr = vdst + ((h*32 + (sel>>1)*8 + tr) * VS2 + (sel&1)*8) * 2;
    uint32_t kaddr = kdst + (((sel&1)*8 + tr) * VS2 + h*128 + (sel>>1)*8) * 2;
    uint32_t paddr = sptr(Ps) + ((grp*16 + (sel&1)*8 + tr) * PS2 + (sel>>1)*8) * 2;

    const float C1 = 0.127517906167328651f;   // (1/sqrt(128)) * log2(e)
    const float C2 = 12.6444645f;             // 22.627417*log2(e) - 20 (shifted)

    const int jn = qt + 1;
    for (int j = 0; j < jn; j++){
        const int s0 = j * 64;
        CPW1();                               // V(j) done; K(j) may be in flight
        __syncthreads();

        // ---- S half: 16 rows x 32 cols (cols h*32..h*32+31) ----
        float sacc[4][4];
        #pragma unroll
        for (int nb = 0; nb < 4; nb++)
            #pragma unroll
            for (int k = 0; k < 4; k++) sacc[nb][k] = 0.f;

        #pragma unroll
        for (int kb2 = 0; kb2 < 16; kb2++){
            uint32_t A[4]; ldsm4(A, qaddr + kb2 * 32);
            #pragma unroll
            for (int sb = 0; sb < 2; sb++){
                uint32_t Bv[4]; ldsm4(Bv, vaddr + sb * 16 * VS2 * 2 + kb2 * 32);
                hmma(sacc[sb*2],     A, Bv[0], Bv[1]);
                hmma(sacc[sb*2 + 1], A, Bv[2], Bv[3]);
            }
        }

        // ---- softmax (shifted static max) + P/L exchange ----
        float pl0 = 0.f, pl1 = 0.f;
        #pragma unroll
        for (int nb = 0; nb < 4; nb++){
            int c0 = s0 + h*32 + nb*8 + 2*q;
            float p0 = (c0     < srow0) ? ex2(fmaf(sacc[nb][0], C1, -C2)) : 0.f;
            float p1 = (c0 + 1 < srow0) ? ex2(fmaf(sacc[nb][1], C1, -C2)) : 0.f;
            float p2 = (c0     < srow1) ? ex2(fmaf(sacc[nb][2], C1, -C2)) : 0.f;
            float p3 = (c0 + 1 < srow1) ? ex2(fmaf(sacc[nb][3], C1, -C2)) : 0.f;
            pl0 += p0 + p1; pl1 += p2 + p3;
            int col = h*32 + nb*8 + 2*q;
            *(uint32_t*)&Ps[lrow * PS2 + col]       = packh2(p0, p1);
            *(uint32_t*)&Ps[(lrow + 8) * PS2 + col] = packh2(p2, p3);
        }
        pl0 += __shfl_xor_sync(~0u, pl0, 1); pl0 += __shfl_xor_sync(~0u, pl0, 2);
        pl1 += __shfl_xor_sync(~0u, pl1, 1); pl1 += __shfl_xor_sync(~0u, pl1, 2);
        if (q == 0){
            Ls[lrow * 2 + h]       = pl0;
            Ls[(lrow + 8) * 2 + h] = pl1;
        }
        __syncthreads();                      // P/L ready; V fully consumed

        if (j + 1 < jn){
            issueV((j + 1) * 64); CPC();      // group: V(j+1)
            CPW1();                           // forces K(j) done; V(j+1) floats
        } else {
            CPW0();                           // last iter: K(j) done
        }

        l0 += Ls[lrow * 2] + Ls[lrow * 2 + 1];
        l1 += Ls[(lrow + 8) * 2] + Ls[(lrow + 8) * 2 + 1];

        // ---- O(16x128) += P . K ; P read back as A-frags ----
        #pragma unroll
        for (int kc = 0; kc < 4; kc++){
            uint32_t P[4]; ldsm4(P, paddr + kc * 32);
            #pragma unroll
            for (int ub = 0; ub < 8; ub++){
                uint32_t Bv[4]; ldsm4t(Bv, kaddr + kc * 16 * VS2 * 2 + ub * 32);
                hmma(oacc[ub*2],     P, Bv[0], Bv[1]);
                hmma(oacc[ub*2 + 1], P, Bv[2], Bv[3]);
            }
        }
        __syncthreads();                      // all done with Ks/Ps
        if (j + 1 < jn){ issueK((j + 1) * 64); CPC(); }   // group: K(j+1)
    }

    // ---- epilogue: normalize; row t==0 forced to zeros ----
    const float inv0 = (srow0 == 0) ? 0.f : 1.f / l0;
    const float inv1 = 1.f / l1;
    float* o0 = out + ((size_t)b * NT + srow0) * NU;
    float* o1 = out + ((size_t)b * NT + srow1) * NU;
    #pragma unroll
    for (int e = 0; e < 16; e++){
        int c = h*128 + (e >> 1)*16 + (e & 1)*8 + 2*q;
        float2 v0, v1;
        v0.x = oacc[e][0] * inv0; v0.y = oacc[e][1] * inv0;
        v1.x = oacc[e][2] * inv1; v1.y = oacc[e][3] * inv1;
        *(float2*)&o0[c] = v0;
        *(float2*)&o1[c] = v1;
    }
}

// ---------------------------------------------------------------------------
extern "C" void kernel_launch(void* const* d_in, const int* in_sizes, int n_in,
                              void* d_out, int out_size)
{
    const float* x  = (const float*)d_in[0];
    const float* Wq = (const float*)d_in[1];
    const float* Wv = (const float*)d_in[2];
    const float* Wk = (const float*)d_in[3];
    float* out = (float*)d_out;

    const int smem1 = (128 * XS2 + 128 * WS2) * 2;                       // 102,400 B
    const int smem2 = (64*QS2 + 2*64*VS2 + 64*PS2) * 2 + 64 * 2 * 4;     // 111,104 B
    cudaFuncSetAttribute(proj_kernel, cudaFuncAttributeMaxDynamicSharedMemorySize, smem1);
    cudaFuncSetAttribute(attn_kernel, cudaFuncAttributeMaxDynamicSharedMemorySize, smem2);

    proj_kernel<<<dim3(NBT / 128, 3), 512, smem1>>>(x, Wq, Wv, Wk);
    attn_kernel<<<dim3(32, 16), 256, smem2>>>(out);
}

// round 12
// speedup vs baseline: 3.7809x; 1.0012x over previous
#include <cuda_runtime.h>
#include <cuda_fp16.h>
#include <stdint.h>

#define NBAT 16
#define NT 2048
#define NF 128
#define NU 256
#define NBT (NBAT*NT)

__device__ __half g_q[NBT*NU];
__device__ __half g_v[NBT*NU];
__device__ __half g_k[NBT*NU];

#define XS2 136   // proj X tile stride in halves
#define WS2 264   // proj W tile stride
#define QS2 264   // attn Q stride
#define VS2 264   // attn V/K stride
#define PS2 72    // attn P-exchange stride

__device__ __forceinline__ uint32_t sptr(const void* p){
    return (uint32_t)__cvta_generic_to_shared(p);
}
__device__ __forceinline__ void ldsm4(uint32_t* d, uint32_t a){
    asm volatile("ldmatrix.sync.aligned.m8n8.x4.shared.b16 {%0,%1,%2,%3}, [%4];"
        : "=r"(d[0]),"=r"(d[1]),"=r"(d[2]),"=r"(d[3]) : "r"(a));
}
__device__ __forceinline__ void ldsm4t(uint32_t* d, uint32_t a){
    asm volatile("ldmatrix.sync.aligned.m8n8.x4.trans.shared.b16 {%0,%1,%2,%3}, [%4];"
        : "=r"(d[0]),"=r"(d[1]),"=r"(d[2]),"=r"(d[3]) : "r"(a));
}
__device__ __forceinline__ void hmma(float* d, const uint32_t* A, uint32_t b0, uint32_t b1){
    asm volatile("mma.sync.aligned.m16n8k16.row.col.f32.f16.f16.f32 "
        "{%0,%1,%2,%3}, {%4,%5,%6,%7}, {%8,%9}, {%0,%1,%2,%3};"
        : "+f"(d[0]),"+f"(d[1]),"+f"(d[2]),"+f"(d[3])
        : "r"(A[0]),"r"(A[1]),"r"(A[2]),"r"(A[3]), "r"(b0),"r"(b1));
}
__device__ __forceinline__ uint32_t packh2(float lo, float hi){
    uint32_t r; asm("cvt.rn.f16x2.f32 %0, %1, %2;" : "=r"(r) : "f"(hi), "f"(lo));
    return r;
}
__device__ __forceinline__ float ex2(float x){
    float r; asm("ex2.approx.f32 %0, %1;" : "=f"(r) : "f"(x)); return r;
}
__device__ __forceinline__ float sigmoidf(float x){
    return 1.f / (1.f + __expf(-x));
}
#define CPA(dst, src) asm volatile("cp.async.cg.shared.global [%0], [%1], 16;" \
    :: "r"(dst), "l"(src))
#define CPC() asm volatile("cp.async.commit_group;" ::: "memory")
#define CPW0() asm volatile("cp.async.wait_group 0;" ::: "memory")
#define CPW1() asm volatile("cp.async.wait_group 1;" ::: "memory")

// ---------------------------------------------------------------------------
// Kernel 1: q/v/k = half(sigmoid(x @ W)). 64x256 tile/CTA, 256 thr,
// 2 CTAs/SM (latency hiding). 8 warps = 4 rowgroups x 2 column halves;
// warp: 16 rows x 128 cols (acc 64 regs, 16 indep chains of length 8).
// ---------------------------------------------------------------------------
__global__ __launch_bounds__(256, 2) void proj_kernel(
    const float* __restrict__ x,  const float* __restrict__ Wq,
    const float* __restrict__ Wv, const float* __restrict__ Wk)
{
    extern __shared__ __half smh[];
    __half* Xs = smh;                // 64 x XS2
    __half* Ws = smh + 64 * XS2;     // 128 x WS2 (rows = f, cols = u)

    const int tid = threadIdx.x, w = tid >> 5, lane = tid & 31;
    const int g = lane >> 2, q = lane & 3;
    const int grp = w >> 1, h = w & 1;
    const int tr = lane & 7, sel = lane >> 3;
    const int rb = blockIdx.x * 64, z = blockIdx.y;
    const float* W = (z == 0) ? Wq : (z == 1) ? Wv : Wk;
    __half* Out = (z == 0) ? g_q : (z == 1) ? g_v : g_k;

    #pragma unroll
    for (int i = 0; i < 8; i++){     // X: 64 x 128 floats = 2048 float4
        int idx = tid + i * 256; int r = idx >> 5, c4 = idx & 31;
        float4 v = *(const float4*)&x[(size_t)(rb + r) * NF + c4 * 4];
        uint2 st; st.x = packh2(v.x, v.y); st.y = packh2(v.z, v.w);
        *(uint2*)&Xs[r * XS2 + c4 * 4] = st;
    }
    #pragma unroll
    for (int i = 0; i < 32; i++){    // W: 128 x 256 floats = 8192 float4
        int idx = tid + i * 256; int r = idx >> 6, c4 = idx & 63;
        float4 v = *(const float4*)&W[(size_t)r * NU + c4 * 4];
        uint2 st; st.x = packh2(v.x, v.y); st.y = packh2(v.z, v.w);
        *(uint2*)&Ws[r * WS2 + c4 * 4] = st;
    }
    __syncthreads();

    float acc[16][4];
    #pragma unroll
    for (int e = 0; e < 16; e++)
        #pragma unroll
        for (int k = 0; k < 4; k++) acc[e][k] = 0.f;

    uint32_t xaddr = sptr(Xs) + ((grp*16 + (sel&1)*8 + tr) * XS2 + (sel>>1)*8) * 2;
    uint32_t waddr = sptr(Ws) + (((sel&1)*8 + tr) * WS2 + h*128 + (sel>>1)*8) * 2;

    #pragma unroll
    for (int kb = 0; kb < 8; kb++){
        uint32_t A[4]; ldsm4(A, xaddr + kb * 32);
        #pragma unroll
        for (int ub = 0; ub < 8; ub++){
            uint32_t Bv[4]; ldsm4t(Bv, waddr + kb * 16 * WS2 * 2 + ub * 32);
            hmma(acc[ub*2],     A, Bv[0], Bv[1]);
            hmma(acc[ub*2 + 1], A, Bv[2], Bv[3]);
        }
    }

    const int r0 = rb + grp * 16 + g, r1 = r0 + 8;
    #pragma unroll
    for (int e = 0; e < 16; e++){
        int c = h*128 + (e >> 1)*16 + (e & 1)*8 + 2*q;
        uint32_t lo = packh2(sigmoidf(acc[e][0]), sigmoidf(acc[e][1]));
        uint32_t hi = packh2(sigmoidf(acc[e][2]), sigmoidf(acc[e][3]));
        *(uint32_t*)&Out[(size_t)r0 * NU + c] = lo;
        *(uint32_t*)&Out[(size_t)r1 * NU + c] = hi;
    }
}

// ---------------------------------------------------------------------------
// Kernel 2: flash attention. 64-query tiles, 256 thr, 2 CTAs/SM. Warp computes
// half of S (16x32) with K-dim SPLIT into two accumulator sets (8 indep HMMA
// chains of length 8 instead of 4 x 16 -> 2x S-phase ILP). Full P via smem
// exchange. V/K separate cp.async groups with selective waits. Shifted static
// softmax max cancels in O/l.
// ---------------------------------------------------------------------------
__global__ __launch_bounds__(256, 2) void attn_kernel(float* __restrict__ out)
{
    extern __shared__ __half smh[];
    __half* Qs = smh;                       // 64 x QS2
    __half* Vs = smh + 64 * QS2;            // 64 x VS2
    __half* Ks = Vs + 64 * VS2;             // 64 x VS2
    __half* Ps = Ks + 64 * VS2;             // 64 x PS2
    float*  Ls = (float*)(Ps + 64 * PS2);   // 64 x 2 row-sum partials

    const int tid = threadIdx.x, w = tid >> 5, lane = tid & 31;
    const int g = lane >> 2, q = lane & 3;
    const int grp = w >> 1, h = w & 1;
    const int tr = lane & 7, sel = lane >> 3;
    const int qt = 31 - (int)blockIdx.x;    // big tiles first
    const int b  = blockIdx.y;
    const int t0 = qt * 64;
    const int lrow = grp * 16 + g;
    const int srow0 = t0 + lrow, srow1 = srow0 + 8;

    const __half* qb = g_q + (size_t)(b * NT) * NU;
    const __half* vb = g_v + (size_t)(b * NT) * NU;
    const __half* kb = g_k + (size_t)(b * NT) * NU;

    const int cr = tid >> 5, cc = tid & 31;
    const uint32_t vdst = sptr(Vs), kdst = sptr(Ks);
    auto issueV = [&](int s0){
        #pragma unroll
        for (int i = 0; i < 8; i++){
            int r = cr + i * 8;
            CPA(vdst + (uint32_t)(r * VS2 * 2 + cc * 16),
                (const char*)&vb[(size_t)(s0 + r) * NU] + cc * 16);
        }
    };
    auto issueK = [&](int s0){
        #pragma unroll
        for (int i = 0; i < 8; i++){
            int r = cr + i * 8;
            CPA(kdst + (uint32_t)(r * VS2 * 2 + cc * 16),
                (const char*)&kb[(size_t)(s0 + r) * NU] + cc * 16);
        }
    };

    issueV(0); CPC();                       // group: V(0)
    issueK(0); CPC();                       // group: K(0)

    #pragma unroll
    for (int i = 0; i < 8; i++){            // Q tile 64 x 256 (overlaps copies)
        int idx = tid + i * 256; int r = idx >> 5, c8 = idx & 31;
        *(uint4*)&Qs[r * QS2 + c8 * 8] =
            *(const uint4*)&qb[(size_t)(t0 + r) * NU + c8 * 8];
    }

    float oacc[16][4];
    #pragma unroll
    for (int e = 0; e < 16; e++)
        #pragma unroll
        for (int k = 0; k < 4; k++) oacc[e][k] = 0.f;
    float l0 = 0.f, l1 = 0.f;

    uint32_t qaddr = sptr(Qs) + ((lrow - g + (sel&1)*8 + tr) * QS2 + (sel>>1)*8) * 2;
    uint32_t vaddr = vdst + ((h*32 + (sel>>1)*8 + tr) * VS2 + (sel&1)*8) * 2;
    uint32_t kaddr = kdst + (((sel&1)*8 + tr) * VS2 + h*128 + (sel>>1)*8) * 2;
    uint32_t paddr = sptr(Ps) + ((grp*16 + (sel&1)*8 + tr) * PS2 + (sel>>1)*8) * 2;

    const float C1 = 0.127517906167328651f;   // (1/sqrt(128)) * log2(e)
    const float C2 = 12.6444645f;             // 22.627417*log2(e) - 20 (shifted)

    const int jn = qt + 1;
    for (int j = 0; j < jn; j++){
        const int s0 = j * 64;
        CPW1();                               // V(j) done; K(j) may be in flight
        __syncthreads();

        // ---- S half: 16 rows x 32 cols; K-dim split -> 8 indep chains ----
        float sacc[4][4], sbcc[4][4];
        #pragma unroll
        for (int nb = 0; nb < 4; nb++)
            #pragma unroll
            for (int k = 0; k < 4; k++){ sacc[nb][k] = 0.f; sbcc[nb][k] = 0.f; }

        #pragma unroll
        for (int kb2 = 0; kb2 < 8; kb2++){
            uint32_t A0[4]; ldsm4(A0, qaddr + kb2 * 32);
            uint32_t A1[4]; ldsm4(A1, qaddr + (kb2 + 8) * 32);
            #pragma unroll
            for (int sb = 0; sb < 2; sb++){
                uint32_t B0[4]; ldsm4(B0, vaddr + sb * 16 * VS2 * 2 + kb2 * 32);
                uint32_t B1[4]; ldsm4(B1, vaddr + sb * 16 * VS2 * 2 + (kb2 + 8) * 32);
                hmma(sacc[sb*2],     A0, B0[0], B0[1]);
                hmma(sacc[sb*2 + 1], A0, B0[2], B0[3]);
                hmma(sbcc[sb*2],     A1, B1[0], B1[1]);
                hmma(sbcc[sb*2 + 1], A1, B1[2], B1[3]);
            }
        }
        #pragma unroll
        for (int nb = 0; nb < 4; nb++)
            #pragma unroll
            for (int k = 0; k < 4; k++) sacc[nb][k] += sbcc[nb][k];

        // ---- softmax (shifted static max) + P/L exchange ----
        float pl0 = 0.f, pl1 = 0.f;
        #pragma unroll
        for (int nb = 0; nb < 4; nb++){
            int c0 = s0 + h*32 + nb*8 + 2*q;
            float p0 = (c0     < srow0) ? ex2(fmaf(sacc[nb][0], C1, -C2)) : 0.f;
            float p1 = (c0 + 1 < srow0) ? ex2(fmaf(sacc[nb][1], C1, -C2)) : 0.f;
            float p2 = (c0     < srow1) ? ex2(fmaf(sacc[nb][2], C1, -C2)) : 0.f;
            float p3 = (c0 + 1 < srow1) ? ex2(fmaf(sacc[nb][3], C1, -C2)) : 0.f;
            pl0 += p0 + p1; pl1 += p2 + p3;
            int col = h*32 + nb*8 + 2*q;
            *(uint32_t*)&Ps[lrow * PS2 + col]       = packh2(p0, p1);
            *(uint32_t*)&Ps[(lrow + 8) * PS2 + col] = packh2(p2, p3);
        }
        pl0 += __shfl_xor_sync(~0u, pl0, 1); pl0 += __shfl_xor_sync(~0u, pl0, 2);
        pl1 += __shfl_xor_sync(~0u, pl1, 1); pl1 += __shfl_xor_sync(~0u, pl1, 2);
        if (q == 0){
            Ls[lrow * 2 + h]       = pl0;
            Ls[(lrow + 8) * 2 + h] = pl1;
        }
        __syncthreads();                      // P/L ready; V fully consumed

        if (j + 1 < jn){
            issueV((j + 1) * 64); CPC();      // group: V(j+1)
            CPW1();                           // forces K(j) done; V(j+1) floats
        } else {
            CPW0();                           // last iter: K(j) done
        }

        l0 += Ls[lrow * 2] + Ls[lrow * 2 + 1];
        l1 += Ls[(lrow + 8) * 2] + Ls[(lrow + 8) * 2 + 1];

        // ---- O(16x128) += P . K ; P read back as A-frags ----
        #pragma unroll
        for (int kc = 0; kc < 4; kc++){
            uint32_t P[4]; ldsm4(P, paddr + kc * 32);
            #pragma unroll
            for (int ub = 0; ub < 8; ub++){
                uint32_t Bv[4]; ldsm4t(Bv, kaddr + kc * 16 * VS2 * 2 + ub * 32);
                hmma(oacc[ub*2],     P, Bv[0], Bv[1]);
                hmma(oacc[ub*2 + 1], P, Bv[2], Bv[3]);
            }
        }
        __syncthreads();                      // all done with Ks/Ps
        if (j + 1 < jn){ issueK((j + 1) * 64); CPC(); }   // group: K(j+1)
    }

    // ---- epilogue: normalize; row t==0 forced to zeros ----
    const float inv0 = (srow0 == 0) ? 0.f : 1.f / l0;
    const float inv1 = 1.f / l1;
    float* o0 = out + ((size_t)b * NT + srow0) * NU;
    float* o1 = out + ((size_t)b * NT + srow1) * NU;
    #pragma unroll
    for (int e = 0; e < 16; e++){
        int c = h*128 + (e >> 1)*16 + (e & 1)*8 + 2*q;
        float2 v0, v1;
        v0.x = oacc[e][0] * inv0; v0.y = oacc[e][1] * inv0;
        v1.x = oacc[e][2] * inv1; v1.y = oacc[e][3] * inv1;
        *(float2*)&o0[c] = v0;
        *(float2*)&o1[c] = v1;
    }
}

// ---------------------------------------------------------------------------
extern "C" void kernel_launch(void* const* d_in, const int* in_sizes, int n_in,
                              void* d_out, int out_size)
{
    const float* x  = (const float*)d_in[0];
    const float* Wq = (const float*)d_in[1];
    const float* Wv = (const float*)d_in[2];
    const float* Wk = (const float*)d_in[3];
    float* out = (float*)d_out;

    const int smem1 = (64 * XS2 + 128 * WS2) * 2;                        // 84,992 B
    const int smem2 = (64*QS2 + 2*64*VS2 + 64*PS2) * 2 + 64 * 2 * 4;     // 111,104 B
    cudaFuncSetAttribute(proj_kernel, cudaFuncAttributeMaxDynamicSharedMemorySize, smem1);
    cudaFuncSetAttribute(attn_kernel, cudaFuncAttributeMaxDynamicSharedMemorySize, smem2);

    proj_kernel<<<dim3(NBT / 64, 3), 256, smem1>>>(x, Wq, Wv, Wk);
    attn_kernel<<<dim3(32, 16), 256, smem2>>>(out);
}

// round 13
// speedup vs baseline: 4.1493x; 1.0975x over previous
#include <cuda_runtime.h>
#include <cuda_fp16.h>
#include <stdint.h>

#define NBAT 16
#define NT 2048
#define NF 128
#define NU 256
#define NBT (NBAT*NT)

__device__ __half g_q[NBT*NU];
__device__ __half g_v[NBT*NU];
__device__ __half g_k[NBT*NU];

#define XS2 136
#define WS2 264
#define QS2 264
#define VS2 264
#define PS2 72

__device__ __forceinline__ uint32_t sptr(const void* p){
    return (uint32_t)__cvta_generic_to_shared(p);
}
__device__ __forceinline__ void ldsm4(uint32_t* d, uint32_t a){
    asm volatile("ldmatrix.sync.aligned.m8n8.x4.shared.b16 {%0,%1,%2,%3}, [%4];"
        : "=r"(d[0]),"=r"(d[1]),"=r"(d[2]),"=r"(d[3]) : "r"(a));
}
__device__ __forceinline__ void ldsm4t(uint32_t* d, uint32_t a){
    asm volatile("ldmatrix.sync.aligned.m8n8.x4.trans.shared.b16 {%0,%1,%2,%3}, [%4];"
        : "=r"(d[0]),"=r"(d[1]),"=r"(d[2]),"=r"(d[3]) : "r"(a));
}
__device__ __forceinline__ void hmma(float* d, const uint32_t* A, uint32_t b0, uint32_t b1){
    asm volatile("mma.sync.aligned.m16n8k16.row.col.f32.f16.f16.f32 "
        "{%0,%1,%2,%3}, {%4,%5,%6,%7}, {%8,%9}, {%0,%1,%2,%3};"
        : "+f"(d[0]),"+f"(d[1]),"+f"(d[2]),"+f"(d[3])
        : "r"(A[0]),"r"(A[1]),"r"(A[2]),"r"(A[3]), "r"(b0),"r"(b1));
}
__device__ __forceinline__ uint32_t packh2(float lo, float hi){
    uint32_t r; asm("cvt.rn.f16x2.f32 %0, %1, %2;" : "=r"(r) : "f"(hi), "f"(lo));
    return r;
}
__device__ __forceinline__ float ex2(float x){
    float r; asm("ex2.approx.f32 %0, %1;" : "=f"(r) : "f"(x)); return r;
}
__device__ __forceinline__ float sigmoidf(float x){
    return 1.f / (1.f + __expf(-x));
}
#define CPA(dst, src) asm volatile("cp.async.cg.shared.global [%0], [%1], 16;" \
    :: "r"(dst), "l"(src))
#define CPC() asm volatile("cp.async.commit_group;" ::: "memory")
#define CPW0() asm volatile("cp.async.wait_group 0;" ::: "memory")

// ---------------------------------------------------------------------------
// Kernel 1: q/v/k = half(sigmoid(x @ W)). 64x256 tile/CTA, 256 thr, 2 CTAs/SM.
// ---------------------------------------------------------------------------
__global__ __launch_bounds__(256, 2) void proj_kernel(
    const float* __restrict__ x,  const float* __restrict__ Wq,
    const float* __restrict__ Wv, const float* __restrict__ Wk)
{
    extern __shared__ __half smh[];
    __half* Xs = smh;
    __half* Ws = smh + 64 * XS2;

    const int tid = threadIdx.x, w = tid >> 5, lane = tid & 31;
    const int g = lane >> 2, q = lane & 3;
    const int grp = w >> 1, h = w & 1;
    const int tr = lane & 7, sel = lane >> 3;
    const int rb = blockIdx.x * 64, z = blockIdx.y;
    const float* W = (z == 0) ? Wq : (z == 1) ? Wv : Wk;
    __half* Out = (z == 0) ? g_q : (z == 1) ? g_v : g_k;

    #pragma unroll
    for (int i = 0; i < 8; i++){
        int idx = tid + i * 256; int r = idx >> 5, c4 = idx & 31;
        float4 v = *(const float4*)&x[(size_t)(rb + r) * NF + c4 * 4];
        uint2 st; st.x = packh2(v.x, v.y); st.y = packh2(v.z, v.w);
        *(uint2*)&Xs[r * XS2 + c4 * 4] = st;
    }
    #pragma unroll
    for (int i = 0; i < 32; i++){
        int idx = tid + i * 256; int r = idx >> 6, c4 = idx & 63;
        float4 v = *(const float4*)&W[(size_t)r * NU + c4 * 4];
        uint2 st; st.x = packh2(v.x, v.y); st.y = packh2(v.z, v.w);
        *(uint2*)&Ws[r * WS2 + c4 * 4] = st;
    }
    __syncthreads();

    float acc[16][4];
    #pragma unroll
    for (int e = 0; e < 16; e++)
        #pragma unroll
        for (int k = 0; k < 4; k++) acc[e][k] = 0.f;

    uint32_t xaddr = sptr(Xs) + ((grp*16 + (sel&1)*8 + tr) * XS2 + (sel>>1)*8) * 2;
    uint32_t waddr = sptr(Ws) + (((sel&1)*8 + tr) * WS2 + h*128 + (sel>>1)*8) * 2;

    #pragma unroll
    for (int kb = 0; kb < 8; kb++){
        uint32_t A[4]; ldsm4(A, xaddr + kb * 32);
        #pragma unroll
        for (int ub = 0; ub < 8; ub++){
            uint32_t Bv[4]; ldsm4t(Bv, waddr + kb * 16 * WS2 * 2 + ub * 32);
            hmma(acc[ub*2],     A, Bv[0], Bv[1]);
            hmma(acc[ub*2 + 1], A, Bv[2], Bv[3]);
        }
    }

    const int r0 = rb + grp * 16 + g, r1 = r0 + 8;
    #pragma unroll
    for (int e = 0; e < 16; e++){
        int c = h*128 + (e >> 1)*16 + (e & 1)*8 + 2*q;
        uint32_t lo = packh2(sigmoidf(acc[e][0]), sigmoidf(acc[e][1]));
        uint32_t hi = packh2(sigmoidf(acc[e][2]), sigmoidf(acc[e][3]));
        *(uint32_t*)&Out[(size_t)r0 * NU + c] = lo;
        *(uint32_t*)&Out[(size_t)r1 * NU + c] = hi;
    }
}

// ---------------------------------------------------------------------------
// Kernel 2: flash attention with PAIRED causal tiles (qt=31-bx then qt=bx:
// exactly 33 key-iters/CTA, 256 CTAs = one balanced wave at 2 CTAs/SM) and
// TWO barriers per iteration:
//   CPW0(V); syncA (V visible; Ks/Ps reuse safe); issueK(j)  [hid by S+smax]
//   CPW0(K); syncB (K/P/Ls visible; Vs reuse safe); issueV(j+1) [hid by O]
// Warp computes half of S (16x32, split-K ILP); full P via smem exchange.
// Shifted static softmax max cancels in O/l.
// ---------------------------------------------------------------------------
__global__ __launch_bounds__(256, 2) void attn_kernel(float* __restrict__ out)
{
    extern __shared__ __half smh[];
    __half* Qs = smh;                       // 64 x QS2
    __half* Vs = smh + 64 * QS2;            // 64 x VS2
    __half* Ks = Vs + 64 * VS2;             // 64 x VS2
    __half* Ps = Ks + 64 * VS2;             // 64 x PS2
    float*  Ls = (float*)(Ps + 64 * PS2);   // 64 x 2 row-sum partials

    const int tid = threadIdx.x, w = tid >> 5, lane = tid & 31;
    const int g = lane >> 2, q = lane & 3;
    const int grp = w >> 1, h = w & 1;
    const int tr = lane & 7, sel = lane >> 3;
    const int bx = blockIdx.x;              // 0..15
    const int b  = blockIdx.y;
    const int lrow = grp * 16 + g;

    const __half* qb = g_q + (size_t)(b * NT) * NU;
    const __half* vb = g_v + (size_t)(b * NT) * NU;
    const __half* kb = g_k + (size_t)(b * NT) * NU;

    const int cr = tid >> 5, cc = tid & 31;
    const uint32_t vdst = sptr(Vs), kdst = sptr(Ks);
    auto issueV = [&](int s0){
        #pragma unroll
        for (int i = 0; i < 8; i++){
            int r = cr + i * 8;
            CPA(vdst + (uint32_t)(r * VS2 * 2 + cc * 16),
                (const char*)&vb[(size_t)(s0 + r) * NU] + cc * 16);
        }
    };
    auto issueK = [&](int s0){
        #pragma unroll
        for (int i = 0; i < 8; i++){
            int r = cr + i * 8;
            CPA(kdst + (uint32_t)(r * VS2 * 2 + cc * 16),
                (const char*)&kb[(size_t)(s0 + r) * NU] + cc * 16);
        }
    };

    uint32_t qaddr = sptr(Qs) + ((grp*16 + (sel&1)*8 + tr) * QS2 + (sel>>1)*8) * 2;
    uint32_t vaddr = vdst + ((h*32 + (sel>>1)*8 + tr) * VS2 + (sel&1)*8) * 2;
    uint32_t kaddr = kdst + (((sel&1)*8 + tr) * VS2 + h*128 + (sel>>1)*8) * 2;
    uint32_t paddr = sptr(Ps) + ((grp*16 + (sel&1)*8 + tr) * PS2 + (sel>>1)*8) * 2;

    const float C1 = 0.127517906167328651f;   // (1/sqrt(128)) * log2(e)
    const float C2 = 12.6444645f;             // 22.627417*log2(e) - 20 (shifted)

    #pragma unroll 1
    for (int ph = 0; ph < 2; ph++){
        const int qt = ph ? bx : 31 - bx;     // big tile first
        const int t0 = qt * 64;
        const int srow0 = t0 + lrow, srow1 = srow0 + 8;
        const int jn = qt + 1;

        __syncthreads();                      // phase boundary: buffers free
        issueV(0); CPC();                     // group: V(0) of this phase

        #pragma unroll
        for (int i = 0; i < 8; i++){          // Q tile 64 x 256 (overlaps copy)
            int idx = tid + i * 256; int r = idx >> 5, c8 = idx & 31;
            *(uint4*)&Qs[r * QS2 + c8 * 8] =
                *(const uint4*)&qb[(size_t)(t0 + r) * NU + c8 * 8];
        }

        float oacc[16][4];
        #pragma unroll
        for (int e = 0; e < 16; e++)
            #pragma unroll
            for (int k = 0; k < 4; k++) oacc[e][k] = 0.f;
        float l0 = 0.f, l1 = 0.f;

        #pragma unroll 1
        for (int j = 0; j < jn; j++){
            const int s0 = j * 64;
            CPW0();                           // V(j) landed (only group out)
            __syncthreads();                  // A: V visible; Ks/Ps reuse safe
            issueK(s0); CPC();                // K(j): hidden behind S+softmax

            float sacc[4][4], sbcc[4][4];
            #pragma unroll
            for (int nb = 0; nb < 4; nb++)
                #pragma unroll
                for (int k = 0; k < 4; k++){ sacc[nb][k] = 0.f; sbcc[nb][k] = 0.f; }

            #pragma unroll
            for (int kb2 = 0; kb2 < 8; kb2++){
                uint32_t A0[4]; ldsm4(A0, qaddr + kb2 * 32);
                uint32_t A1[4]; ldsm4(A1, qaddr + (kb2 + 8) * 32);
                #pragma unroll
                for (int sb = 0; sb < 2; sb++){
                    uint32_t B0[4]; ldsm4(B0, vaddr + sb * 16 * VS2 * 2 + kb2 * 32);
                    uint32_t B1[4]; ldsm4(B1, vaddr + sb * 16 * VS2 * 2 + (kb2 + 8) * 32);
                    hmma(sacc[sb*2],     A0, B0[0], B0[1]);
                    hmma(sacc[sb*2 + 1], A0, B0[2], B0[3]);
                    hmma(sbcc[sb*2],     A1, B1[0], B1[1]);
                    hmma(sbcc[sb*2 + 1], A1, B1[2], B1[3]);
                }
            }
            #pragma unroll
            for (int nb = 0; nb < 4; nb++)
                #pragma unroll
                for (int k = 0; k < 4; k++) sacc[nb][k] += sbcc[nb][k];

            float pl0 = 0.f, pl1 = 0.f;
            #pragma unroll
            for (int nb = 0; nb < 4; nb++){
                int c0 = s0 + h*32 + nb*8 + 2*q;
                float p0 = (c0     < srow0) ? ex2(fmaf(sacc[nb][0], C1, -C2)) : 0.f;
                float p1 = (c0 + 1 < srow0) ? ex2(fmaf(sacc[nb][1], C1, -C2)) : 0.f;
                float p2 = (c0     < srow1) ? ex2(fmaf(sacc[nb][2], C1, -C2)) : 0.f;
                float p3 = (c0 + 1 < srow1) ? ex2(fmaf(sacc[nb][3], C1, -C2)) : 0.f;
                pl0 += p0 + p1; pl1 += p2 + p3;
                int col = h*32 + nb*8 + 2*q;
                *(uint32_t*)&Ps[lrow * PS2 + col]       = packh2(p0, p1);
                *(uint32_t*)&Ps[(lrow + 8) * PS2 + col] = packh2(p2, p3);
            }
            pl0 += __shfl_xor_sync(~0u, pl0, 1); pl0 += __shfl_xor_sync(~0u, pl0, 2);
            pl1 += __shfl_xor_sync(~0u, pl1, 1); pl1 += __shfl_xor_sync(~0u, pl1, 2);
            if (q == 0){
                Ls[lrow * 2 + h]       = pl0;
                Ls[(lrow + 8) * 2 + h] = pl1;
            }

            CPW0();                           // K(j) landed (only group out)
            __syncthreads();                  // B: K/P/Ls visible; Vs reuse safe
            if (j + 1 < jn){ issueV(s0 + 64); CPC(); }

            l0 += Ls[lrow * 2] + Ls[lrow * 2 + 1];
            l1 += Ls[(lrow + 8) * 2] + Ls[(lrow + 8) * 2 + 1];

            #pragma unroll
            for (int kc = 0; kc < 4; kc++){
                uint32_t P[4]; ldsm4(P, paddr + kc * 32);
                #pragma unroll
                for (int ub = 0; ub < 8; ub++){
                    uint32_t Bv[4]; ldsm4t(Bv, kaddr + kc * 16 * VS2 * 2 + ub * 32);
                    hmma(oacc[ub*2],     P, Bv[0], Bv[1]);
                    hmma(oacc[ub*2 + 1], P, Bv[2], Bv[3]);
                }
            }
        }

        const float inv0 = (srow0 == 0) ? 0.f : 1.f / l0;
        const float inv1 = 1.f / l1;
        float* o0 = out + ((size_t)b * NT + srow0) * NU;
        float* o1 = out + ((size_t)b * NT + srow1) * NU;
        #pragma unroll
        for (int e = 0; e < 16; e++){
            int c = h*128 + (e >> 1)*16 + (e & 1)*8 + 2*q;
            float2 v0, v1;
            v0.x = oacc[e][0] * inv0; v0.y = oacc[e][1] * inv0;
            v1.x = oacc[e][2] * inv1; v1.y = oacc[e][3] * inv1;
            *(float2*)&o0[c] = v0;
            *(float2*)&o1[c] = v1;
        }
    }
}

// ---------------------------------------------------------------------------
extern "C" void kernel_launch(void* const* d_in, const int* in_sizes, int n_in,
                              void* d_out, int out_size)
{
    const float* x  = (const float*)d_in[0];
    const float* Wq = (const float*)d_in[1];
    const float* Wv = (const float*)d_in[2];
    const float* Wk = (const float*)d_in[3];
    float* out = (float*)d_out;

    const int smem1 = (64 * XS2 + 128 * WS2) * 2;                        // 84,992 B
    const int smem2 = (64*QS2 + 2*64*VS2 + 64*PS2) * 2 + 64 * 2 * 4;     // 111,104 B
    cudaFuncSetAttribute(proj_kernel, cudaFuncAttributeMaxDynamicSharedMemorySize, smem1);
    cudaFuncSetAttribute(attn_kernel, cudaFuncAttributeMaxDynamicSharedMemorySize, smem2);

    proj_kernel<<<dim3(NBT / 64, 3), 256, smem1>>>(x, Wq, Wv, Wk);
    attn_kernel<<<dim3(16, 16), 256, smem2>>>(out);
}

// round 14
// speedup vs baseline: 4.1747x; 1.0061x over previous
#include <cuda_runtime.h>
#include <cuda_fp16.h>
#include <stdint.h>

#define NBAT 16
#define NT 2048
#define NF 128
#define NU 256
#define NBT (NBAT*NT)

__device__ __half g_q[NBT*NU];
__device__ __half g_v[NBT*NU];
__device__ __half g_k[NBT*NU];
__device__ __half g_x[(size_t)NBT*NF];   // fp16 copy of x
__device__ __half g_w[3*NF*NU];          // fp16 copies of Wq/Wv/Wk

#define XS2 136
#define WS2 264
#define QS2 264
#define VS2 264
#define PS2 72

__device__ __forceinline__ uint32_t sptr(const void* p){
    return (uint32_t)__cvta_generic_to_shared(p);
}
__device__ __forceinline__ void ldsm4(uint32_t* d, uint32_t a){
    asm volatile("ldmatrix.sync.aligned.m8n8.x4.shared.b16 {%0,%1,%2,%3}, [%4];"
        : "=r"(d[0]),"=r"(d[1]),"=r"(d[2]),"=r"(d[3]) : "r"(a));
}
__device__ __forceinline__ void ldsm4t(uint32_t* d, uint32_t a){
    asm volatile("ldmatrix.sync.aligned.m8n8.x4.trans.shared.b16 {%0,%1,%2,%3}, [%4];"
        : "=r"(d[0]),"=r"(d[1]),"=r"(d[2]),"=r"(d[3]) : "r"(a));
}
__device__ __forceinline__ void hmma(float* d, const uint32_t* A, uint32_t b0, uint32_t b1){
    asm volatile("mma.sync.aligned.m16n8k16.row.col.f32.f16.f16.f32 "
        "{%0,%1,%2,%3}, {%4,%5,%6,%7}, {%8,%9}, {%0,%1,%2,%3};"
        : "+f"(d[0]),"+f"(d[1]),"+f"(d[2]),"+f"(d[3])
        : "r"(A[0]),"r"(A[1]),"r"(A[2]),"r"(A[3]), "r"(b0),"r"(b1));
}
__device__ __forceinline__ uint32_t packh2(float lo, float hi){
    uint32_t r; asm("cvt.rn.f16x2.f32 %0, %1, %2;" : "=r"(r) : "f"(hi), "f"(lo));
    return r;
}
__device__ __forceinline__ float ex2(float x){
    float r; asm("ex2.approx.f32 %0, %1;" : "=f"(r) : "f"(x)); return r;
}
__device__ __forceinline__ float sigmoidf(float x){
    return 1.f / (1.f + __expf(-x));
}
#define CPA(dst, src) asm volatile("cp.async.cg.shared.global [%0], [%1], 16;" \
    :: "r"(dst), "l"(src))
#define CPC() asm volatile("cp.async.commit_group;" ::: "memory")
#define CPW0() asm volatile("cp.async.wait_group 0;" ::: "memory")

// ---------------------------------------------------------------------------
// Kernel 0: one-shot fp16 conversion of x and Wq/Wv/Wk (same cvt.rn rounding
// proj previously applied per-CTA -> MMA inputs bit-identical).
// Blocks [0,96): W (24576 float4). Blocks [96,4192): x (1048576 float4).
// ---------------------------------------------------------------------------
__global__ void conv_kernel(const float* __restrict__ x,
                            const float* __restrict__ Wq,
                            const float* __restrict__ Wv,
                            const float* __restrict__ Wk)
{
    int bid = blockIdx.x;
    if (bid < 96){
        int idx = bid * 256 + threadIdx.x;        // float4 index over 3*8192
        int z = idx >> 13, r4 = idx & 8191;
        const float* W = (z == 0) ? Wq : (z == 1) ? Wv : Wk;
        float4 v = *(const float4*)&W[r4 * 4];
        uint2 st; st.x = packh2(v.x, v.y); st.y = packh2(v.z, v.w);
        *(uint2*)&g_w[z * NF * NU + r4 * 4] = st;
    } else {
        size_t idx = (size_t)(bid - 96) * 256 + threadIdx.x;   // float4 index
        float4 v = *(const float4*)&x[idx * 4];
        uint2 st; st.x = packh2(v.x, v.y); st.y = packh2(v.z, v.w);
        *(uint2*)&g_x[idx * 4] = st;
    }
}

// ---------------------------------------------------------------------------
// Kernel 1: q/v/k = half(sigmoid(x @ W)). 64x256 tile/CTA, 256 thr, 2 CTAs/SM.
// Inputs pre-converted fp16; loaded via cp.async (80 KB/CTA, async).
// ---------------------------------------------------------------------------
__global__ __launch_bounds__(256, 2) void proj_kernel()
{
    extern __shared__ __half smh[];
    __half* Xs = smh;                // 64 x XS2
    __half* Ws = smh + 64 * XS2;     // 128 x WS2 (rows = f, cols = u)

    const int tid = threadIdx.x, w = tid >> 5, lane = tid & 31;
    const int g = lane >> 2, q = lane & 3;
    const int grp = w >> 1, h = w & 1;
    const int tr = lane & 7, sel = lane >> 3;
    const int rb = blockIdx.x * 64, z = blockIdx.y;
    const __half* Wg = g_w + z * NF * NU;
    __half* Out = (z == 0) ? g_q : (z == 1) ? g_v : g_k;

    // cp.async W: 128 rows x 32 chunks(16B) = 4096 chunks, 16/thread
    const uint32_t wsb = sptr(Ws), xsb = sptr(Xs);
    #pragma unroll
    for (int i = 0; i < 16; i++){
        int c = tid + i * 256; int r = c >> 5, cc = c & 31;
        CPA(wsb + (uint32_t)(r * WS2 * 2 + cc * 16),
            (const char*)(Wg + (size_t)r * NU) + cc * 16);
    }
    // cp.async X: 64 rows x 16 chunks = 1024 chunks, 4/thread
    #pragma unroll
    for (int i = 0; i < 4; i++){
        int c = tid + i * 256; int r = c >> 4, cc = c & 15;
        CPA(xsb + (uint32_t)(r * XS2 * 2 + cc * 16),
            (const char*)(g_x + (size_t)(rb + r) * NF) + cc * 16);
    }
    CPC(); CPW0();
    __syncthreads();

    float acc[16][4];
    #pragma unroll
    for (int e = 0; e < 16; e++)
        #pragma unroll
        for (int k = 0; k < 4; k++) acc[e][k] = 0.f;

    uint32_t xaddr = xsb + ((grp*16 + (sel&1)*8 + tr) * XS2 + (sel>>1)*8) * 2;
    uint32_t waddr = wsb + (((sel&1)*8 + tr) * WS2 + h*128 + (sel>>1)*8) * 2;

    #pragma unroll
    for (int kb = 0; kb < 8; kb++){
        uint32_t A[4]; ldsm4(A, xaddr + kb * 32);
        #pragma unroll
        for (int ub = 0; ub < 8; ub++){
            uint32_t Bv[4]; ldsm4t(Bv, waddr + kb * 16 * WS2 * 2 + ub * 32);
            hmma(acc[ub*2],     A, Bv[0], Bv[1]);
            hmma(acc[ub*2 + 1], A, Bv[2], Bv[3]);
        }
    }

    const int r0 = rb + grp * 16 + g, r1 = r0 + 8;
    #pragma unroll
    for (int e = 0; e < 16; e++){
        int c = h*128 + (e >> 1)*16 + (e & 1)*8 + 2*q;
        uint32_t lo = packh2(sigmoidf(acc[e][0]), sigmoidf(acc[e][1]));
        uint32_t hi = packh2(sigmoidf(acc[e][2]), sigmoidf(acc[e][3]));
        *(uint32_t*)&Out[(size_t)r0 * NU + c] = lo;
        *(uint32_t*)&Out[(size_t)r1 * NU + c] = hi;
    }
}

// ---------------------------------------------------------------------------
// Kernel 2: flash attention (UNCHANGED from round 13: paired causal tiles,
// 2 barriers/iter, split-K S, P smem exchange, shifted static softmax max).
// ---------------------------------------------------------------------------
__global__ __launch_bounds__(256, 2) void attn_kernel(float* __restrict__ out)
{
    extern __shared__ __half smh[];
    __half* Qs = smh;                       // 64 x QS2
    __half* Vs = smh + 64 * QS2;            // 64 x VS2
    __half* Ks = Vs + 64 * VS2;             // 64 x VS2
    __half* Ps = Ks + 64 * VS2;             // 64 x PS2
    float*  Ls = (float*)(Ps + 64 * PS2);   // 64 x 2 row-sum partials

    const int tid = threadIdx.x, w = tid >> 5, lane = tid & 31;
    const int g = lane >> 2, q = lane & 3;
    const int grp = w >> 1, h = w & 1;
    const int tr = lane & 7, sel = lane >> 3;
    const int bx = blockIdx.x;              // 0..15
    const int b  = blockIdx.y;
    const int lrow = grp * 16 + g;

    const __half* qb = g_q + (size_t)(b * NT) * NU;
    const __half* vb = g_v + (size_t)(b * NT) * NU;
    const __half* kb = g_k + (size_t)(b * NT) * NU;

    const int cr = tid >> 5, cc = tid & 31;
    const uint32_t vdst = sptr(Vs), kdst = sptr(Ks);
    auto issueV = [&](int s0){
        #pragma unroll
        for (int i = 0; i < 8; i++){
            int r = cr + i * 8;
            CPA(vdst + (uint32_t)(r * VS2 * 2 + cc * 16),
                (const char*)&vb[(size_t)(s0 + r) * NU] + cc * 16);
        }
    };
    auto issueK = [&](int s0){
        #pragma unroll
        for (int i = 0; i < 8; i++){
            int r = cr + i * 8;
            CPA(kdst + (uint32_t)(r * VS2 * 2 + cc * 16),
                (const char*)&kb[(size_t)(s0 + r) * NU] + cc * 16);
        }
    };

    uint32_t qaddr = sptr(Qs) + ((grp*16 + (sel&1)*8 + tr) * QS2 + (sel>>1)*8) * 2;
    uint32_t vaddr = vdst + ((h*32 + (sel>>1)*8 + tr) * VS2 + (sel&1)*8) * 2;
    uint32_t kaddr = kdst + (((sel&1)*8 + tr) * VS2 + h*128 + (sel>>1)*8) * 2;
    uint32_t paddr = sptr(Ps) + ((grp*16 + (sel&1)*8 + tr) * PS2 + (sel>>1)*8) * 2;

    const float C1 = 0.127517906167328651f;   // (1/sqrt(128)) * log2(e)
    const float C2 = 12.6444645f;             // 22.627417*log2(e) - 20 (shifted)

    #pragma unroll 1
    for (int ph = 0; ph < 2; ph++){
        const int qt = ph ? bx : 31 - bx;     // big tile first
        const int t0 = qt * 64;
        const int srow0 = t0 + lrow, srow1 = srow0 + 8;
        const int jn = qt + 1;

        __syncthreads();                      // phase boundary: buffers free
        issueV(0); CPC();                     // group: V(0) of this phase

        #pragma unroll
        for (int i = 0; i < 8; i++){          // Q tile 64 x 256 (overlaps copy)
            int idx = tid + i * 256; int r = idx >> 5, c8 = idx & 31;
            *(uint4*)&Qs[r * QS2 + c8 * 8] =
                *(const uint4*)&qb[(size_t)(t0 + r) * NU + c8 * 8];
        }

        float oacc[16][4];
        #pragma unroll
        for (int e = 0; e < 16; e++)
            #pragma unroll
            for (int k = 0; k < 4; k++) oacc[e][k] = 0.f;
        float l0 = 0.f, l1 = 0.f;

        #pragma unroll 1
        for (int j = 0; j < jn; j++){
            const int s0 = j * 64;
            CPW0();                           // V(j) landed (only group out)
            __syncthreads();                  // A: V visible; Ks/Ps reuse safe
            issueK(s0); CPC();                // K(j): hidden behind S+softmax

            float sacc[4][4], sbcc[4][4];
            #pragma unroll
            for (int nb = 0; nb < 4; nb++)
                #pragma unroll
                for (int k = 0; k < 4; k++){ sacc[nb][k] = 0.f; sbcc[nb][k] = 0.f; }

            #pragma unroll
            for (int kb2 = 0; kb2 < 8; kb2++){
                uint32_t A0[4]; ldsm4(A0, qaddr + kb2 * 32);
                uint32_t A1[4]; ldsm4(A1, qaddr + (kb2 + 8) * 32);
                #pragma unroll
                for (int sb = 0; sb < 2; sb++){
                    uint32_t B0[4]; ldsm4(B0, vaddr + sb * 16 * VS2 * 2 + kb2 * 32);
                    uint32_t B1[4]; ldsm4(B1, vaddr + sb * 16 * VS2 * 2 + (kb2 + 8) * 32);
                    hmma(sacc[sb*2],     A0, B0[0], B0[1]);
                    hmma(sacc[sb*2 + 1], A0, B0[2], B0[3]);
                    hmma(sbcc[sb*2],     A1, B1[0], B1[1]);
                    hmma(sbcc[sb*2 + 1], A1, B1[2], B1[3]);
                }
            }
            #pragma unroll
            for (int nb = 0; nb < 4; nb++)
                #pragma unroll
                for (int k = 0; k < 4; k++) sacc[nb][k] += sbcc[nb][k];

            float pl0 = 0.f, pl1 = 0.f;
            #pragma unroll
            for (int nb = 0; nb < 4; nb++){
                int c0 = s0 + h*32 + nb*8 + 2*q;
                float p0 = (c0     < srow0) ? ex2(fmaf(sacc[nb][0], C1, -C2)) : 0.f;
                float p1 = (c0 + 1 < srow0) ? ex2(fmaf(sacc[nb][1], C1, -C2)) : 0.f;
                float p2 = (c0     < srow1) ? ex2(fmaf(sacc[nb][2], C1, -C2)) : 0.f;
                float p3 = (c0 + 1 < srow1) ? ex2(fmaf(sacc[nb][3], C1, -C2)) : 0.f;
                pl0 += p0 + p1; pl1 += p2 + p3;
                int col = h*32 + nb*8 + 2*q;
                *(uint32_t*)&Ps[lrow * PS2 + col]       = packh2(p0, p1);
                *(uint32_t*)&Ps[(lrow + 8) * PS2 + col] = packh2(p2, p3);
            }
            pl0 += __shfl_xor_sync(~0u, pl0, 1); pl0 += __shfl_xor_sync(~0u, pl0, 2);
            pl1 += __shfl_xor_sync(~0u, pl1, 1); pl1 += __shfl_xor_sync(~0u, pl1, 2);
            if (q == 0){
                Ls[lrow * 2 + h]       = pl0;
                Ls[(lrow + 8) * 2 + h] = pl1;
            }

            CPW0();                           // K(j) landed (only group out)
            __syncthreads();                  // B: K/P/Ls visible; Vs reuse safe
            if (j + 1 < jn){ issueV(s0 + 64); CPC(); }

            l0 += Ls[lrow * 2] + Ls[lrow * 2 + 1];
            l1 += Ls[(lrow + 8) * 2] + Ls[(lrow + 8) * 2 + 1];

            #pragma unroll
            for (int kc = 0; kc < 4; kc++){
                uint32_t P[4]; ldsm4(P, paddr + kc * 32);
                #pragma unroll
                for (int ub = 0; ub < 8; ub++){
                    uint32_t Bv[4]; ldsm4t(Bv, kaddr + kc * 16 * VS2 * 2 + ub * 32);
                    hmma(oacc[ub*2],     P, Bv[0], Bv[1]);
                    hmma(oacc[ub*2 + 1], P, Bv[2], Bv[3]);
                }
            }
        }

        const float inv0 = (srow0 == 0) ? 0.f : 1.f / l0;
        const float inv1 = 1.f / l1;
        float* o0 = out + ((size_t)b * NT + srow0) * NU;
        float* o1 = out + ((size_t)b * NT + srow1) * NU;
        #pragma unroll
        for (int e = 0; e < 16; e++){
            int c = h*128 + (e >> 1)*16 + (e & 1)*8 + 2*q;
            float2 v0, v1;
            v0.x = oacc[e][0] * inv0; v0.y = oacc[e][1] * inv0;
            v1.x = oacc[e][2] * inv1; v1.y = oacc[e][3] * inv1;
            *(float2*)&o0[c] = v0;
            *(float2*)&o1[c] = v1;
        }
    }
}

// ---------------------------------------------------------------------------
extern "C" void kernel_launch(void* const* d_in, const int* in_sizes, int n_in,
                              void* d_out, int out_size)
{
    const float* x  = (const float*)d_in[0];
    const float* Wq = (const float*)d_in[1];
    const float* Wv = (const float*)d_in[2];
    const float* Wk = (const float*)d_in[3];
    float* out = (float*)d_out;

    const int smem1 = (64 * XS2 + 128 * WS2) * 2;                        // 84,992 B
    const int smem2 = (64*QS2 + 2*64*VS2 + 64*PS2) * 2 + 64 * 2 * 4;     // 111,104 B
    cudaFuncSetAttribute(proj_kernel, cudaFuncAttributeMaxDynamicSharedMemorySize, smem1);
    cudaFuncSetAttribute(attn_kernel, cudaFuncAttributeMaxDynamicSharedMemorySize, smem2);

    conv_kernel<<<4192, 256>>>(x, Wq, Wv, Wk);
    proj_kernel<<<dim3(NBT / 64, 3), 256, smem1>>>();
    attn_kernel<<<dim3(16, 16), 256, smem2>>>(out);
}

// round 16
// speedup vs baseline: 4.4473x; 1.0653x over previous
#include <cuda_runtime.h>
#include <cuda_fp16.h>
#include <stdint.h>

#define NBAT 16
#define NT 2048
#define NF 128
#define NU 256
#define NBT (NBAT*NT)

__device__ __half g_q[NBT*NU];
__device__ __half g_v[NBT*NU];
__device__ __half g_k[NBT*NU];
__device__ __half g_x[(size_t)NBT*NF];
__device__ __half g_w[3*NF*NU];

#define XS2 136
#define WS2 264
#define QS2 264
#define VS2 264
#define PS2 72

__device__ __forceinline__ uint32_t sptr(const void* p){
    return (uint32_t)__cvta_generic_to_shared(p);
}
__device__ __forceinline__ void ldsm4(uint32_t* d, uint32_t a){
    asm volatile("ldmatrix.sync.aligned.m8n8.x4.shared.b16 {%0,%1,%2,%3}, [%4];"
        : "=r"(d[0]),"=r"(d[1]),"=r"(d[2]),"=r"(d[3]) : "r"(a));
}
__device__ __forceinline__ void ldsm4t(uint32_t* d, uint32_t a){
    asm volatile("ldmatrix.sync.aligned.m8n8.x4.trans.shared.b16 {%0,%1,%2,%3}, [%4];"
        : "=r"(d[0]),"=r"(d[1]),"=r"(d[2]),"=r"(d[3]) : "r"(a));
}
__device__ __forceinline__ void hmma(float* d, const uint32_t* A, uint32_t b0, uint32_t b1){
    asm volatile("mma.sync.aligned.m16n8k16.row.col.f32.f16.f16.f32 "
        "{%0,%1,%2,%3}, {%4,%5,%6,%7}, {%8,%9}, {%0,%1,%2,%3};"
        : "+f"(d[0]),"+f"(d[1]),"+f"(d[2]),"+f"(d[3])
        : "r"(A[0]),"r"(A[1]),"r"(A[2]),"r"(A[3]), "r"(b0),"r"(b1));
}
__device__ __forceinline__ uint32_t packh2(float lo, float hi){
    uint32_t r; asm("cvt.rn.f16x2.f32 %0, %1, %2;" : "=r"(r) : "f"(hi), "f"(lo));
    return r;
}
__device__ __forceinline__ float ex2(float x){
    float r; asm("ex2.approx.f32 %0, %1;" : "=f"(r) : "f"(x)); return r;
}
__device__ __forceinline__ float sigmoidf(float x){
    return 1.f / (1.f + __expf(-x));
}
#define CPA(dst, src) asm volatile("cp.async.cg.shared.global [%0], [%1], 16;" \
    :: "r"(dst), "l"(src))
#define CPC() asm volatile("cp.async.commit_group;" ::: "memory")
#define CPW0() asm volatile("cp.async.wait_group 0;" ::: "memory")

// ---------------------------------------------------------------------------
// Kernel 0: one-shot fp16 conversion of x and Wq/Wv/Wk.
// ---------------------------------------------------------------------------
__global__ void conv_kernel(const float* __restrict__ x,
                            const float* __restrict__ Wq,
                            const float* __restrict__ Wv,
                            const float* __restrict__ Wk)
{
    int bid = blockIdx.x;
    if (bid < 96){
        int idx = bid * 256 + threadIdx.x;
        int z = idx >> 13, r4 = idx & 8191;
        const float* W = (z == 0) ? Wq : (z == 1) ? Wv : Wk;
        float4 v = *(const float4*)&W[r4 * 4];
        uint2 st; st.x = packh2(v.x, v.y); st.y = packh2(v.z, v.w);
        *(uint2*)&g_w[z * NF * NU + r4 * 4] = st;
    } else {
        size_t idx = (size_t)(bid - 96) * 256 + threadIdx.x;
        float4 v = *(const float4*)&x[idx * 4];
        uint2 st; st.x = packh2(v.x, v.y); st.y = packh2(v.z, v.w);
        *(uint2*)&g_x[idx * 4] = st;
    }
}

// ---------------------------------------------------------------------------
// Kernel 1: q/v/k = half(sigmoid(x @ W)). 64x256 tile/CTA, 256 thr, 2 CTAs/SM.
// ---------------------------------------------------------------------------
__global__ __launch_bounds__(256, 2) void proj_kernel()
{
    extern __shared__ __half smh[];
    __half* Xs = smh;
    __half* Ws = smh + 64 * XS2;

    const int tid = threadIdx.x, w = tid >> 5, lane = tid & 31;
    const int g = lane >> 2, q = lane & 3;
    const int grp = w >> 1, h = w & 1;
    const int tr = lane & 7, sel = lane >> 3;
    const int rb = blockIdx.x * 64, z = blockIdx.y;
    const __half* Wg = g_w + z * NF * NU;
    __half* Out = (z == 0) ? g_q : (z == 1) ? g_v : g_k;

    const uint32_t wsb = sptr(Ws), xsb = sptr(Xs);
    #pragma unroll
    for (int i = 0; i < 16; i++){
        int c = tid + i * 256; int r = c >> 5, cc = c & 31;
        CPA(wsb + (uint32_t)(r * WS2 * 2 + cc * 16),
            (const char*)(Wg + (size_t)r * NU) + cc * 16);
    }
    #pragma unroll
    for (int i = 0; i < 4; i++){
        int c = tid + i * 256; int r = c >> 4, cc = c & 15;
        CPA(xsb + (uint32_t)(r * XS2 * 2 + cc * 16),
            (const char*)(g_x + (size_t)(rb + r) * NF) + cc * 16);
    }
    CPC(); CPW0();
    __syncthreads();

    float acc[16][4];
    #pragma unroll
    for (int e = 0; e < 16; e++)
        #pragma unroll
        for (int k = 0; k < 4; k++) acc[e][k] = 0.f;

    uint32_t xaddr = xsb + ((grp*16 + (sel&1)*8 + tr) * XS2 + (sel>>1)*8) * 2;
    uint32_t waddr = wsb + (((sel&1)*8 + tr) * WS2 + h*128 + (sel>>1)*8) * 2;

    #pragma unroll
    for (int kb = 0; kb < 8; kb++){
        uint32_t A[4]; ldsm4(A, xaddr + kb * 32);
        #pragma unroll
        for (int ub = 0; ub < 8; ub++){
            uint32_t Bv[4]; ldsm4t(Bv, waddr + kb * 16 * WS2 * 2 + ub * 32);
            hmma(acc[ub*2],     A, Bv[0], Bv[1]);
            hmma(acc[ub*2 + 1], A, Bv[2], Bv[3]);
        }
    }

    const int r0 = rb + grp * 16 + g, r1 = r0 + 8;
    #pragma unroll
    for (int e = 0; e < 16; e++){
        int c = h*128 + (e >> 1)*16 + (e & 1)*8 + 2*q;
        uint32_t lo = packh2(sigmoidf(acc[e][0]), sigmoidf(acc[e][1]));
        uint32_t hi = packh2(sigmoidf(acc[e][2]), sigmoidf(acc[e][3]));
        *(uint32_t*)&Out[(size_t)r0 * NU + c] = lo;
        *(uint32_t*)&Out[(size_t)r1 * NU + c] = hi;
    }
}

// ---------------------------------------------------------------------------
// Kernel 2: flash attention. Warp tiling: 8 warps = 2 rowgroups(32 rows) x
// 4 column-quarters. S: warp = 32 rows x 16 cols, k-loop covers ALL 16
// k-blocks (u = 0:256) — this was the round-15 bug (8 blocks = half the dot).
// O: warp = 32 rows x 64 cols, B(K) reused across m-tiles (36->24 ldsm/warp).
// Pipeline: paired causal tiles (33 iters/CTA, one balanced wave), 2 barriers
// per iter, V/K separate cp.async groups. Shifted static softmax max.
// ---------------------------------------------------------------------------
__global__ __launch_bounds__(256, 2) void attn_kernel(float* __restrict__ out)
{
    extern __shared__ __half smh[];
    __half* Qs = smh;                       // 64 x QS2
    __half* Vs = smh + 64 * QS2;            // 64 x VS2
    __half* Ks = Vs + 64 * VS2;             // 64 x VS2
    __half* Ps = Ks + 64 * VS2;             // 64 x PS2
    float*  Ls = (float*)(Ps + 64 * PS2);   // 64 x 4 row-sum partials

    const int tid = threadIdx.x, w = tid >> 5, lane = tid & 31;
    const int g = lane >> 2, q = lane & 3;
    const int grp = w >> 2;                 // 0..1 rowgroup (32 rows)
    const int qd  = w & 3;                  // 0..3 column quarter
    const int tr = lane & 7, sel = lane >> 3;
    const int bx = blockIdx.x;              // 0..15
    const int b  = blockIdx.y;

    const __half* qb = g_q + (size_t)(b * NT) * NU;
    const __half* vb = g_v + (size_t)(b * NT) * NU;
    const __half* kb = g_k + (size_t)(b * NT) * NU;

    const int cr = tid >> 5, cc = tid & 31;
    const uint32_t vdst = sptr(Vs), kdst = sptr(Ks);
    auto issueV = [&](int s0){
        #pragma unroll
        for (int i = 0; i < 8; i++){
            int r = cr + i * 8;
            CPA(vdst + (uint32_t)(r * VS2 * 2 + cc * 16),
                (const char*)&vb[(size_t)(s0 + r) * NU] + cc * 16);
        }
    };
    auto issueK = [&](int s0){
        #pragma unroll
        for (int i = 0; i < 8; i++){
            int r = cr + i * 8;
            CPA(kdst + (uint32_t)(r * VS2 * 2 + cc * 16),
                (const char*)&kb[(size_t)(s0 + r) * NU] + cc * 16);
        }
    };

    uint32_t qaddr = sptr(Qs) + ((grp*32 + (sel&1)*8 + tr) * QS2 + (sel>>1)*8) * 2;
    uint32_t vaddr = vdst + ((qd*16 + (sel>>1)*8 + tr) * VS2 + (sel&1)*8) * 2;
    uint32_t kaddr = kdst + (((sel&1)*8 + tr) * VS2 + qd*64 + (sel>>1)*8) * 2;
    uint32_t paddr = sptr(Ps) + ((grp*32 + (sel&1)*8 + tr) * PS2 + (sel>>1)*8) * 2;

    const float C1 = 0.127517906167328651f;   // (1/sqrt(128)) * log2(e)
    const float C2 = 12.6444645f;             // 22.627417*log2(e) - 20 (shifted)

    #pragma unroll 1
    for (int ph = 0; ph < 2; ph++){
        const int qt = ph ? bx : 31 - bx;     // big tile first
        const int t0 = qt * 64;
        const int jn = qt + 1;
        const int rA0 = t0 + grp*32 + g,      rA1 = rA0 + 8;     // mt=0
        const int rB0 = rA0 + 16,             rB1 = rB0 + 8;     // mt=1

        __syncthreads();                      // phase boundary: buffers free
        issueV(0); CPC();                     // group: V(0) of this phase

        #pragma unroll
        for (int i = 0; i < 8; i++){          // Q tile 64 x 256 (overlaps copy)
            int idx = tid + i * 256; int r = idx >> 5, c8 = idx & 31;
            *(uint4*)&Qs[r * QS2 + c8 * 8] =
                *(const uint4*)&qb[(size_t)(t0 + r) * NU + c8 * 8];
        }

        float oacc[2][8][4];
        #pragma unroll
        for (int mt = 0; mt < 2; mt++)
            #pragma unroll
            for (int e = 0; e < 8; e++)
                #pragma unroll
                for (int k = 0; k < 4; k++) oacc[mt][e][k] = 0.f;
        float lA0 = 0.f, lA1 = 0.f, lB0 = 0.f, lB1 = 0.f;

        #pragma unroll 1
        for (int j = 0; j < jn; j++){
            const int s0 = j * 64;
            CPW0();                           // V(j) landed (only group out)
            __syncthreads();                  // A: V visible; Ks/Ps reuse safe
            issueK(s0); CPC();                // K(j): hidden behind S+softmax

            // ---- S: warp = 32 rows x 16 cols; FULL k range (16 blocks) ----
            float sacc[2][2][4];
            #pragma unroll
            for (int mt = 0; mt < 2; mt++)
                #pragma unroll
                for (int nt = 0; nt < 2; nt++)
                    #pragma unroll
                    for (int k = 0; k < 4; k++) sacc[mt][nt][k] = 0.f;

            #pragma unroll
            for (int kb2 = 0; kb2 < 16; kb2++){
                uint32_t A0[4]; ldsm4(A0, qaddr + kb2 * 32);
                uint32_t A1[4]; ldsm4(A1, qaddr + 16 * QS2 * 2 + kb2 * 32);
                uint32_t Bv[4]; ldsm4(Bv, vaddr + kb2 * 32);
                hmma(sacc[0][0], A0, Bv[0], Bv[1]);
                hmma(sacc[0][1], A0, Bv[2], Bv[3]);
                hmma(sacc[1][0], A1, Bv[0], Bv[1]);
                hmma(sacc[1][1], A1, Bv[2], Bv[3]);
            }

            // ---- softmax (shifted static max) + P store + 4-way L partials ----
            float plA0 = 0.f, plA1 = 0.f, plB0 = 0.f, plB1 = 0.f;
            #pragma unroll
            for (int mt = 0; mt < 2; mt++){
                const int r0 = mt ? rB0 : rA0;
                const int r1 = mt ? rB1 : rA1;
                #pragma unroll
                for (int nt = 0; nt < 2; nt++){
                    int c0 = s0 + qd*16 + nt*8 + 2*q;
                    float p0 = (c0     < r0) ? ex2(fmaf(sacc[mt][nt][0], C1, -C2)) : 0.f;
                    float p1 = (c0 + 1 < r0) ? ex2(fmaf(sacc[mt][nt][1], C1, -C2)) : 0.f;
                    float p2 = (c0     < r1) ? ex2(fmaf(sacc[mt][nt][2], C1, -C2)) : 0.f;
                    float p3 = (c0 + 1 < r1) ? ex2(fmaf(sacc[mt][nt][3], C1, -C2)) : 0.f;
                    if (mt){ plB0 += p0 + p1; plB1 += p2 + p3; }
                    else   { plA0 += p0 + p1; plA1 += p2 + p3; }
                    int col = qd*16 + nt*8 + 2*q;
                    int lr = grp*32 + mt*16 + g;
                    *(uint32_t*)&Ps[lr * PS2 + col]       = packh2(p0, p1);
                    *(uint32_t*)&Ps[(lr + 8) * PS2 + col] = packh2(p2, p3);
                }
            }
            plA0 += __shfl_xor_sync(~0u, plA0, 1); plA0 += __shfl_xor_sync(~0u, plA0, 2);
            plA1 += __shfl_xor_sync(~0u, plA1, 1); plA1 += __shfl_xor_sync(~0u, plA1, 2);
            plB0 += __shfl_xor_sync(~0u, plB0, 1); plB0 += __shfl_xor_sync(~0u, plB0, 2);
            plB1 += __shfl_xor_sync(~0u, plB1, 1); plB1 += __shfl_xor_sync(~0u, plB1, 2);
            if (q == 0){
                int lr = grp*32 + g;
                Ls[(lr      ) * 4 + qd] = plA0;
                Ls[(lr +  8 ) * 4 + qd] = plA1;
                Ls[(lr + 16 ) * 4 + qd] = plB0;
                Ls[(lr + 24 ) * 4 + qd] = plB1;
            }

            CPW0();                           // K(j) landed (only group out)
            __syncthreads();                  // B: K/P/Ls visible; Vs reuse safe
            if (j + 1 < jn){ issueV(s0 + 64); CPC(); }

            {
                int lr = grp*32 + g;
                float4 a0 = *(float4*)&Ls[(lr      ) * 4];
                float4 a1 = *(float4*)&Ls[(lr +  8 ) * 4];
                float4 b0 = *(float4*)&Ls[(lr + 16 ) * 4];
                float4 b1 = *(float4*)&Ls[(lr + 24 ) * 4];
                lA0 += a0.x + a0.y + a0.z + a0.w;
                lA1 += a1.x + a1.y + a1.z + a1.w;
                lB0 += b0.x + b0.y + b0.z + b0.w;
                lB1 += b1.x + b1.y + b1.z + b1.w;
            }

            // ---- O: warp = 32 rows x 64 cols; B(K) reused across m-tiles ----
            #pragma unroll
            for (int kc = 0; kc < 4; kc++){
                uint32_t P0[4]; ldsm4(P0, paddr + kc * 32);
                uint32_t P1[4]; ldsm4(P1, paddr + 16 * PS2 * 2 + kc * 32);
                #pragma unroll
                for (int ub = 0; ub < 4; ub++){
                    uint32_t Bv[4]; ldsm4t(Bv, kaddr + kc * 16 * VS2 * 2 + ub * 32);
                    hmma(oacc[0][ub*2],     P0, Bv[0], Bv[1]);
                    hmma(oacc[0][ub*2 + 1], P0, Bv[2], Bv[3]);
                    hmma(oacc[1][ub*2],     P1, Bv[0], Bv[1]);
                    hmma(oacc[1][ub*2 + 1], P1, Bv[2], Bv[3]);
                }
            }
        }

        // ---- epilogue: normalize; row t==0 forced to zeros ----
        float invA0 = (rA0 == 0) ? 0.f : 1.f / lA0;
        float invA1 = 1.f / lA1;
        float invB0 = 1.f / lB0;
        float invB1 = 1.f / lB1;
        #pragma unroll
        for (int mt = 0; mt < 2; mt++){
            const int r0 = mt ? rB0 : rA0;
            const int r1 = mt ? rB1 : rA1;
            const float i0 = mt ? invB0 : invA0;
            const float i1 = mt ? invB1 : invA1;
            float* o0 = out + ((size_t)b * NT + r0) * NU;
            float* o1 = out + ((size_t)b * NT + r1) * NU;
            #pragma unroll
            for (int e = 0; e < 8; e++){
                int c = qd*64 + e*8 + 2*q;
                float2 v0, v1;
                v0.x = oacc[mt][e][0] * i0; v0.y = oacc[mt][e][1] * i0;
                v1.x = oacc[mt][e][2] * i1; v1.y = oacc[mt][e][3] * i1;
                *(float2*)&o0[c] = v0;
                *(float2*)&o1[c] = v1;
            }
        }
    }
}

// ---------------------------------------------------------------------------
extern "C" void kernel_launch(void* const* d_in, const int* in_sizes, int n_in,
                              void* d_out, int out_size)
{
    const float* x  = (const float*)d_in[0];
    const float* Wq = (const float*)d_in[1];
    const float* Wv = (const float*)d_in[2];
    const float* Wk = (const float*)d_in[3];
    float* out = (float*)d_out;

    const int smem1 = (64 * XS2 + 128 * WS2) * 2;                        // 84,992 B
    const int smem2 = (64*QS2 + 2*64*VS2 + 64*PS2) * 2 + 64 * 4 * 4;     // 111,616 B
    cudaFuncSetAttribute(proj_kernel, cudaFuncAttributeMaxDynamicSharedMemorySize, smem1);
    cudaFuncSetAttribute(attn_kernel, cudaFuncAttributeMaxDynamicSharedMemorySize, smem2);

    conv_kernel<<<4192, 256>>>(x, Wq, Wv, Wk);
    proj_kernel<<<dim3(NBT / 64, 3), 256, smem1>>>();
    attn_kernel<<<dim3(16, 16), 256, smem2>>>(out);
}